// round 2
// baseline (speedup 1.0000x reference)
#include <cuda_runtime.h>
#include <math.h>

// Problem constants
#define B_     64
#define NTOK   256
#define C_     1024
#define H_     16
#define DH_    64
#define DFF_   4096
#define MTOK   (B_*NTOK)          // 16384 tokens
#define EPS_   1e-5f

// ---------------------------------------------------------------------------
// Scratch (static __device__ allocations; allowed per harness rules)
// ---------------------------------------------------------------------------
__device__ float g_ln  [(size_t)MTOK * C_];        //  64 MB (reused ln1/ln2)
__device__ float g_qkv [(size_t)MTOK * 3 * C_];    // 192 MB
__device__ float g_S   [(size_t)B_ * H_ * NTOK * NTOK]; // 268 MB scores/probs
__device__ float g_attn[(size_t)MTOK * C_];        //  64 MB merged attn out
__device__ float g_x1  [(size_t)MTOK * C_];        //  64 MB post-attn residual
__device__ float g_ff  [(size_t)MTOK * DFF_];      // 256 MB MLP hidden

// ---------------------------------------------------------------------------
// LayerNorm: one block per token, 256 threads, one float4 each (C=1024)
// ---------------------------------------------------------------------------
__global__ __launch_bounds__(256) void ln_kernel(
    const float* __restrict__ x, const float* __restrict__ g,
    const float* __restrict__ b, float* __restrict__ out)
{
    const int t   = blockIdx.x;
    const int tid = threadIdx.x;
    const float4 v = reinterpret_cast<const float4*>(x + (size_t)t * C_)[tid];

    float s  = v.x + v.y + v.z + v.w;
    float ss = v.x*v.x + v.y*v.y + v.z*v.z + v.w*v.w;

    __shared__ float rs[256], rq[256];
    rs[tid] = s; rq[tid] = ss;
    __syncthreads();
    #pragma unroll
    for (int o = 128; o > 0; o >>= 1) {
        if (tid < o) { rs[tid] += rs[tid + o]; rq[tid] += rq[tid + o]; }
        __syncthreads();
    }
    const float mu  = rs[0] * (1.0f / C_);
    const float var = rq[0] * (1.0f / C_) - mu * mu;
    const float inv = rsqrtf(var + EPS_);

    const float4 gv = reinterpret_cast<const float4*>(g)[tid];
    const float4 bv = reinterpret_cast<const float4*>(b)[tid];
    float4 o4;
    o4.x = (v.x - mu) * inv * gv.x + bv.x;
    o4.y = (v.y - mu) * inv * gv.y + bv.y;
    o4.z = (v.z - mu) * inv * gv.z + bv.z;
    o4.w = (v.w - mu) * inv * gv.w + bv.w;
    reinterpret_cast<float4*>(out + (size_t)t * C_)[tid] = o4;
}

// ---------------------------------------------------------------------------
// Tiled SGEMM: out[M,N] = A[M,K] @ W[K,N] + bias (+gelu | +residual)
// 128x128 block tile, BK=8, 256 threads, 8x8 per-thread microtile (4+4 split)
// ---------------------------------------------------------------------------
enum { EPI_BIAS = 0, EPI_GELU = 1, EPI_RES = 2 };

__device__ __forceinline__ float gelu_tanh(float x) {
    const float k0 = 0.7978845608028654f;   // sqrt(2/pi)
    float x3 = x * x * x;
    return 0.5f * x * (1.0f + tanhf(k0 * (x + 0.044715f * x3)));
}

template <int EPI>
__global__ __launch_bounds__(256) void sgemm128(
    const float* __restrict__ A, const float* __restrict__ W,
    const float* __restrict__ bias, const float* __restrict__ res,
    float* __restrict__ out, int M, int N, int K)
{
    __shared__ float As[8][128];   // A tile, transposed: As[k][m]
    __shared__ float Bs[8][128];   // W tile: Bs[k][n]

    const int tid  = threadIdx.x;
    const int tx   = tid & 15;     // 16 col groups
    const int ty   = tid >> 4;     // 16 row groups
    const int row0 = blockIdx.y * 128;
    const int col0 = blockIdx.x * 128;

    const int aRow = tid >> 1;           // 0..127
    const int aCol = (tid & 1) * 4;      // 0 or 4
    const int bRow = tid >> 5;           // 0..7
    const int bCol = (tid & 31) * 4;     // 0..124

    const float* Ap = A + (size_t)(row0 + aRow) * K + aCol;
    const float* Wp = W + (size_t)bRow * N + col0 + bCol;

    float acc[8][8];
    #pragma unroll
    for (int i = 0; i < 8; i++)
        #pragma unroll
        for (int j = 0; j < 8; j++) acc[i][j] = 0.0f;

    for (int k0 = 0; k0 < K; k0 += 8) {
        float4 av = *reinterpret_cast<const float4*>(Ap + k0);
        float4 bv = *reinterpret_cast<const float4*>(Wp + (size_t)k0 * N);
        As[aCol + 0][aRow] = av.x;
        As[aCol + 1][aRow] = av.y;
        As[aCol + 2][aRow] = av.z;
        As[aCol + 3][aRow] = av.w;
        *reinterpret_cast<float4*>(&Bs[bRow][bCol]) = bv;   // 128-stride rows: 16B aligned
        __syncthreads();

        #pragma unroll
        for (int kk = 0; kk < 8; kk++) {
            float4 a0 = *reinterpret_cast<const float4*>(&As[kk][ty * 4]);
            float4 a1 = *reinterpret_cast<const float4*>(&As[kk][64 + ty * 4]);
            float4 b0 = *reinterpret_cast<const float4*>(&Bs[kk][tx * 4]);
            float4 b1 = *reinterpret_cast<const float4*>(&Bs[kk][64 + tx * 4]);
            float ar[8] = {a0.x, a0.y, a0.z, a0.w, a1.x, a1.y, a1.z, a1.w};
            float br[8] = {b0.x, b0.y, b0.z, b0.w, b1.x, b1.y, b1.z, b1.w};
            #pragma unroll
            for (int i = 0; i < 8; i++)
                #pragma unroll
                for (int j = 0; j < 8; j++)
                    acc[i][j] = fmaf(ar[i], br[j], acc[i][j]);
        }
        __syncthreads();
    }

    #pragma unroll
    for (int i = 0; i < 8; i++) {
        const int r = row0 + ((i < 4) ? (ty * 4 + i) : (64 + ty * 4 + i - 4));
        #pragma unroll
        for (int j = 0; j < 8; j++) {
            const int c = col0 + ((j < 4) ? (tx * 4 + j) : (64 + tx * 4 + j - 4));
            float v = acc[i][j] + bias[c];
            if (EPI == EPI_GELU) v = gelu_tanh(v);
            if (EPI == EPI_RES)  v += res[(size_t)r * N + c];
            out[(size_t)r * N + c] = v;
        }
    }
}

// ---------------------------------------------------------------------------
// Attention scores: S[bh,n,m] = 0.125 * (Q[n,:] . K[m,:]) + relpos_bias
// Per block: one (b,h), 64x64 output tile; full Dh=64 loaded to smem.
// qkv layout per token row (3072): [q(h*64+d) | k(+1024) | v(+2048)]
// NOTE: smem tiles padded to 65 floats/row -> scalar stores (float4 would be
// misaligned at odd rows: (r*65+c)*4 bytes is not 16B-aligned).
// ---------------------------------------------------------------------------
__global__ __launch_bounds__(256) void scores_kernel(
    const float* __restrict__ qkv, const int* __restrict__ rel_idx,
    const float* __restrict__ rel_bias, float* __restrict__ S)
{
    __shared__ float Qs[64][65];
    __shared__ float Ks[64][65];

    const int bh = blockIdx.x;
    const int b  = bh >> 4, h = bh & 15;
    const int n0 = blockIdx.y * 64;
    const int m0 = blockIdx.z * 64;
    const int tid = threadIdx.x;
    const int tx = tid & 15, ty = tid >> 4;

    #pragma unroll
    for (int it = 0; it < 4; it++) {
        const int r = (tid >> 4) + it * 16;
        const int c = (tid & 15) * 4;
        float4 qv = *reinterpret_cast<const float4*>(
            qkv + (size_t)(b * NTOK + n0 + r) * (3 * C_) + h * DH_ + c);
        Qs[r][c + 0] = qv.x; Qs[r][c + 1] = qv.y;
        Qs[r][c + 2] = qv.z; Qs[r][c + 3] = qv.w;
        float4 kv = *reinterpret_cast<const float4*>(
            qkv + (size_t)(b * NTOK + m0 + r) * (3 * C_) + C_ + h * DH_ + c);
        Ks[r][c + 0] = kv.x; Ks[r][c + 1] = kv.y;
        Ks[r][c + 2] = kv.z; Ks[r][c + 3] = kv.w;
    }
    __syncthreads();

    float acc[4][4] = {};
    #pragma unroll 8
    for (int kk = 0; kk < 64; kk++) {
        float ar[4], br[4];
        #pragma unroll
        for (int i = 0; i < 4; i++) ar[i] = Qs[ty * 4 + i][kk];
        #pragma unroll
        for (int j = 0; j < 4; j++) br[j] = Ks[tx * 4 + j][kk];
        #pragma unroll
        for (int i = 0; i < 4; i++)
            #pragma unroll
            for (int j = 0; j < 4; j++)
                acc[i][j] = fmaf(ar[i], br[j], acc[i][j]);
    }

    #pragma unroll
    for (int i = 0; i < 4; i++) {
        const int n = n0 + ty * 4 + i;
        #pragma unroll
        for (int j = 0; j < 4; j++) {
            const int m = m0 + tx * 4 + j;
            const float bb = rel_bias[rel_idx[n * NTOK + m] * H_ + h];
            S[((size_t)bh * NTOK + n) * NTOK + m] = acc[i][j] * 0.125f + bb;
        }
    }
}

// ---------------------------------------------------------------------------
// Row softmax over 256 elements: one block per (bh, n) row.
// ---------------------------------------------------------------------------
__global__ __launch_bounds__(256) void softmax_kernel(float* __restrict__ S)
{
    float* p = S + (size_t)blockIdx.x * NTOK;
    const int tid = threadIdx.x;
    const float v = p[tid];

    __shared__ float red[256];
    red[tid] = v;
    __syncthreads();
    #pragma unroll
    for (int o = 128; o > 0; o >>= 1) {
        if (tid < o) red[tid] = fmaxf(red[tid], red[tid + o]);
        __syncthreads();
    }
    const float mx = red[0];
    __syncthreads();

    const float e = __expf(v - mx);
    red[tid] = e;
    __syncthreads();
    #pragma unroll
    for (int o = 128; o > 0; o >>= 1) {
        if (tid < o) red[tid] += red[tid + o];
        __syncthreads();
    }
    p[tid] = e / red[0];
}

// ---------------------------------------------------------------------------
// PV: out[token, h*64+d] = sum_m P[bh,n,m] * V[bh,m,d]
// Per block: one (b,h), 64 query rows x full Dh=64; loop m in 64-chunks.
// ---------------------------------------------------------------------------
__global__ __launch_bounds__(256) void pv_kernel(
    const float* __restrict__ S, const float* __restrict__ qkv,
    float* __restrict__ attn_out)
{
    __shared__ float Ps[64][65];
    __shared__ float Vs[64][65];

    const int bh = blockIdx.x;
    const int b  = bh >> 4, h = bh & 15;
    const int n0 = blockIdx.y * 64;
    const int tid = threadIdx.x;
    const int tx = tid & 15, ty = tid >> 4;

    float acc[4][4] = {};

    for (int m0 = 0; m0 < NTOK; m0 += 64) {
        #pragma unroll
        for (int it = 0; it < 4; it++) {
            const int r = (tid >> 4) + it * 16;
            const int c = (tid & 15) * 4;
            float4 pv = *reinterpret_cast<const float4*>(
                S + ((size_t)bh * NTOK + n0 + r) * NTOK + m0 + c);
            Ps[r][c + 0] = pv.x; Ps[r][c + 1] = pv.y;
            Ps[r][c + 2] = pv.z; Ps[r][c + 3] = pv.w;
            float4 vv = *reinterpret_cast<const float4*>(
                qkv + (size_t)(b * NTOK + m0 + r) * (3 * C_) + 2 * C_ + h * DH_ + c);
            Vs[r][c + 0] = vv.x; Vs[r][c + 1] = vv.y;
            Vs[r][c + 2] = vv.z; Vs[r][c + 3] = vv.w;
        }
        __syncthreads();

        #pragma unroll 8
        for (int mm = 0; mm < 64; mm++) {
            float ar[4], br[4];
            #pragma unroll
            for (int i = 0; i < 4; i++) ar[i] = Ps[ty * 4 + i][mm];
            #pragma unroll
            for (int j = 0; j < 4; j++) br[j] = Vs[mm][tx * 4 + j];
            #pragma unroll
            for (int i = 0; i < 4; i++)
                #pragma unroll
                for (int j = 0; j < 4; j++)
                    acc[i][j] = fmaf(ar[i], br[j], acc[i][j]);
        }
        __syncthreads();
    }

    #pragma unroll
    for (int i = 0; i < 4; i++) {
        const int n = n0 + ty * 4 + i;
        #pragma unroll
        for (int j = 0; j < 4; j++) {
            const int d = tx * 4 + j;
            attn_out[(size_t)(b * NTOK + n) * C_ + h * DH_ + d] = acc[i][j];
        }
    }
}

// ---------------------------------------------------------------------------
// Launch
// ---------------------------------------------------------------------------
extern "C" void kernel_launch(void* const* d_in, const int* in_sizes, int n_in,
                              void* d_out, int out_size)
{
    const float* x        = (const float*)d_in[0];
    const int*   rel_idx  = (const int*)  d_in[1];
    const float* qkv_w    = (const float*)d_in[2];
    const float* qkv_b    = (const float*)d_in[3];
    const float* proj_w   = (const float*)d_in[4];
    const float* proj_b   = (const float*)d_in[5];
    const float* rel_bias = (const float*)d_in[6];
    const float* ln1_g    = (const float*)d_in[7];
    const float* ln1_b    = (const float*)d_in[8];
    const float* ln2_g    = (const float*)d_in[9];
    const float* ln2_b    = (const float*)d_in[10];
    const float* fc1_w    = (const float*)d_in[11];
    const float* fc1_b    = (const float*)d_in[12];
    const float* fc2_w    = (const float*)d_in[13];
    const float* fc2_b    = (const float*)d_in[14];
    float* out = (float*)d_out;

    float *ln, *qkv, *S, *attn, *x1, *ff;
    cudaGetSymbolAddress((void**)&ln,   g_ln);
    cudaGetSymbolAddress((void**)&qkv,  g_qkv);
    cudaGetSymbolAddress((void**)&S,    g_S);
    cudaGetSymbolAddress((void**)&attn, g_attn);
    cudaGetSymbolAddress((void**)&x1,   g_x1);
    cudaGetSymbolAddress((void**)&ff,   g_ff);

    // 1) LN1
    ln_kernel<<<MTOK, 256>>>(x, ln1_g, ln1_b, ln);
    // 2) QKV GEMM: [16384,1024] @ [1024,3072] + b
    sgemm128<EPI_BIAS><<<dim3(3 * C_ / 128, MTOK / 128), 256>>>(
        ln, qkv_w, qkv_b, nullptr, qkv, MTOK, 3 * C_, C_);
    // 3) scores + rel-pos bias
    scores_kernel<<<dim3(B_ * H_, NTOK / 64, NTOK / 64), 256>>>(
        qkv, rel_idx, rel_bias, S);
    // 4) softmax rows
    softmax_kernel<<<B_ * H_ * NTOK, 256>>>(S);
    // 5) P @ V, merge heads
    pv_kernel<<<dim3(B_ * H_, NTOK / 64), 256>>>(S, qkv, attn);
    // 6) proj + residual(x)
    sgemm128<EPI_RES><<<dim3(C_ / 128, MTOK / 128), 256>>>(
        attn, proj_w, proj_b, x, x1, MTOK, C_, C_);
    // 7) LN2
    ln_kernel<<<MTOK, 256>>>(x1, ln2_g, ln2_b, ln);
    // 8) FC1 + GELU
    sgemm128<EPI_GELU><<<dim3(DFF_ / 128, MTOK / 128), 256>>>(
        ln, fc1_w, fc1_b, nullptr, ff, MTOK, DFF_, C_);
    // 9) FC2 + residual(x1) -> out
    sgemm128<EPI_RES><<<dim3(C_ / 128, MTOK / 128), 256>>>(
        ff, fc2_w, fc2_b, x1, out, MTOK, C_, DFF_);
}

// round 4
// speedup vs baseline: 1.3939x; 1.3939x over previous
#include <cuda_runtime.h>
#include <math.h>
#include <mma.h>

using namespace nvcuda;

// Problem constants
#define B_     64
#define NTOK   256
#define C_     1024
#define H_     16
#define DH_    64
#define DFF_   4096
#define MTOK   (B_*NTOK)          // 16384 tokens
#define EPS_   1e-5f

// ---------------------------------------------------------------------------
// Scratch
// ---------------------------------------------------------------------------
__device__ float g_ln  [(size_t)MTOK * C_];
__device__ float g_qkv [(size_t)MTOK * 3 * C_];
__device__ float g_S   [(size_t)B_ * H_ * NTOK * NTOK];   // softmax probs P
__device__ float g_attn[(size_t)MTOK * C_];
__device__ float g_x1  [(size_t)MTOK * C_];
__device__ float g_ff  [(size_t)MTOK * DFF_];

// ---------------------------------------------------------------------------
// LayerNorm (unchanged, known-correct)
// ---------------------------------------------------------------------------
__global__ __launch_bounds__(256) void ln_kernel(
    const float* __restrict__ x, const float* __restrict__ g,
    const float* __restrict__ b, float* __restrict__ out)
{
    const int t   = blockIdx.x;
    const int tid = threadIdx.x;
    const float4 v = reinterpret_cast<const float4*>(x + (size_t)t * C_)[tid];

    float s  = v.x + v.y + v.z + v.w;
    float ss = v.x*v.x + v.y*v.y + v.z*v.z + v.w*v.w;

    __shared__ float rs[256], rq[256];
    rs[tid] = s; rq[tid] = ss;
    __syncthreads();
    #pragma unroll
    for (int o = 128; o > 0; o >>= 1) {
        if (tid < o) { rs[tid] += rs[tid + o]; rq[tid] += rq[tid + o]; }
        __syncthreads();
    }
    const float mu  = rs[0] * (1.0f / C_);
    const float var = rq[0] * (1.0f / C_) - mu * mu;
    const float inv = rsqrtf(var + EPS_);

    const float4 gv = reinterpret_cast<const float4*>(g)[tid];
    const float4 bv = reinterpret_cast<const float4*>(b)[tid];
    float4 o4;
    o4.x = (v.x - mu) * inv * gv.x + bv.x;
    o4.y = (v.y - mu) * inv * gv.y + bv.y;
    o4.z = (v.z - mu) * inv * gv.z + bv.z;
    o4.w = (v.w - mu) * inv * gv.w + bv.w;
    reinterpret_cast<float4*>(out + (size_t)t * C_)[tid] = o4;
}

// ---------------------------------------------------------------------------
// TF32 WMMA GEMM: out[M,N] = A[M,K] @ W[K,N] + bias (+gelu | +residual)
// 128x128 block tile, BK=16, 256 threads = 8 warps.
// Warp grid 2x4: each warp computes 64x32 = 4x2 m16n16k8 fragments.
// ---------------------------------------------------------------------------
enum { EPI_BIAS = 0, EPI_GELU = 1, EPI_RES = 2 };

__device__ __forceinline__ float gelu_tanh(float x) {
    const float k0 = 0.7978845608028654f;   // sqrt(2/pi)
    float x3 = x * x * x;
    return 0.5f * x * (1.0f + tanhf(k0 * (x + 0.044715f * x3)));
}

#define LDA_S 24   // As row stride (floats): 96B, 32B-aligned rows
#define LDB_S 136  // Bs row stride: 544B, 32B-aligned rows
#define LDC_S 40   // stage row stride: 160B, 32B-aligned rows

template <int EPI>
__global__ __launch_bounds__(256) void wgemm128(
    const float* __restrict__ A, const float* __restrict__ W,
    const float* __restrict__ bias, const float* __restrict__ res,
    float* __restrict__ out, int M, int N, int K)
{
    __shared__ __align__(32) float As[128][LDA_S];   // A tile row-major [m][k]
    __shared__ __align__(32) float Bs[16][LDB_S];    // W tile row-major [k][n]
    __shared__ __align__(32) float Cst[8][16][LDC_S];// per-warp epilogue stage

    const int tid  = threadIdx.x;
    const int wid  = tid >> 5;
    const int lane = tid & 31;
    const int warp_m = wid & 1;       // 0..1 -> 64-row slab
    const int warp_n = wid >> 1;      // 0..3 -> 32-col slab
    const int row0 = blockIdx.y * 128;
    const int col0 = blockIdx.x * 128;

    // A loader: row = tid>>1 (0..127), col = (tid&1)*8
    const int arow = tid >> 1;
    const int acol = (tid & 1) * 8;
    const float* Ap = A + (size_t)(row0 + arow) * K + acol;
    // B loader: row = tid>>4 (0..15), col = (tid&15)*8
    const int brow = tid >> 4;
    const int bcol = (tid & 15) * 8;
    const float* Wp = W + (size_t)brow * N + col0 + bcol;

    wmma::fragment<wmma::accumulator, 16, 16, 8, float> c[4][2];
    #pragma unroll
    for (int mi = 0; mi < 4; mi++)
        #pragma unroll
        for (int nj = 0; nj < 2; nj++)
            wmma::fill_fragment(c[mi][nj], 0.0f);

    for (int k0 = 0; k0 < K; k0 += 16) {
        // load + convert to tf32
        float4 a0 = *reinterpret_cast<const float4*>(Ap + k0);
        float4 a1 = *reinterpret_cast<const float4*>(Ap + k0 + 4);
        float4 b0 = *reinterpret_cast<const float4*>(Wp + (size_t)k0 * N);
        float4 b1 = *reinterpret_cast<const float4*>(Wp + (size_t)k0 * N + 4);
        float4 at0, at1, bt0, bt1;
        at0.x = wmma::__float_to_tf32(a0.x); at0.y = wmma::__float_to_tf32(a0.y);
        at0.z = wmma::__float_to_tf32(a0.z); at0.w = wmma::__float_to_tf32(a0.w);
        at1.x = wmma::__float_to_tf32(a1.x); at1.y = wmma::__float_to_tf32(a1.y);
        at1.z = wmma::__float_to_tf32(a1.z); at1.w = wmma::__float_to_tf32(a1.w);
        bt0.x = wmma::__float_to_tf32(b0.x); bt0.y = wmma::__float_to_tf32(b0.y);
        bt0.z = wmma::__float_to_tf32(b0.z); bt0.w = wmma::__float_to_tf32(b0.w);
        bt1.x = wmma::__float_to_tf32(b1.x); bt1.y = wmma::__float_to_tf32(b1.y);
        bt1.z = wmma::__float_to_tf32(b1.z); bt1.w = wmma::__float_to_tf32(b1.w);
        *reinterpret_cast<float4*>(&As[arow][acol])     = at0;
        *reinterpret_cast<float4*>(&As[arow][acol + 4]) = at1;
        *reinterpret_cast<float4*>(&Bs[brow][bcol])     = bt0;
        *reinterpret_cast<float4*>(&Bs[brow][bcol + 4]) = bt1;
        __syncthreads();

        #pragma unroll
        for (int kk = 0; kk < 16; kk += 8) {
            wmma::fragment<wmma::matrix_a, 16, 16, 8, wmma::precision::tf32, wmma::row_major> af[4];
            wmma::fragment<wmma::matrix_b, 16, 16, 8, wmma::precision::tf32, wmma::row_major> bf[2];
            #pragma unroll
            for (int mi = 0; mi < 4; mi++)
                wmma::load_matrix_sync(af[mi], &As[warp_m * 64 + mi * 16][kk], LDA_S);
            #pragma unroll
            for (int nj = 0; nj < 2; nj++)
                wmma::load_matrix_sync(bf[nj], &Bs[kk][warp_n * 32 + nj * 16], LDB_S);
            #pragma unroll
            for (int mi = 0; mi < 4; mi++)
                #pragma unroll
                for (int nj = 0; nj < 2; nj++)
                    wmma::mma_sync(c[mi][nj], af[mi], bf[nj], c[mi][nj]);
        }
        __syncthreads();
    }

    // Epilogue: stage each 16x32 slab to smem, then coalesced global writes
    const int cg = col0 + warp_n * 32 + lane;       // this lane's global col
    const float bv = bias[cg];
    #pragma unroll
    for (int mi = 0; mi < 4; mi++) {
        wmma::store_matrix_sync(&Cst[wid][0][0],  c[mi][0], LDC_S, wmma::mem_row_major);
        wmma::store_matrix_sync(&Cst[wid][0][16], c[mi][1], LDC_S, wmma::mem_row_major);
        __syncwarp();
        const int rg0 = row0 + warp_m * 64 + mi * 16;
        #pragma unroll
        for (int rr = 0; rr < 16; rr++) {
            const int rg = rg0 + rr;
            float v = Cst[wid][rr][lane] + bv;
            if (EPI == EPI_GELU) v = gelu_tanh(v);
            if (EPI == EPI_RES)  v += res[(size_t)rg * N + cg];
            out[(size_t)rg * N + cg] = v;
        }
        __syncwarp();
    }
}

// ---------------------------------------------------------------------------
// Fused scores + relpos bias + softmax.
// Per block: one (b,h) and 64 query rows. Loops K chunks of 64, keeps the full
// 256-wide score row slice in registers, softmaxes across the 16 lanes that
// share a row, writes P directly.
// ---------------------------------------------------------------------------
__global__ __launch_bounds__(256) void scores_softmax_kernel(
    const float* __restrict__ qkv, const int* __restrict__ rel_idx,
    const float* __restrict__ rel_bias, float* __restrict__ P)
{
    __shared__ float Qs[64][65];
    __shared__ float Ks[64][65];

    const int bh = blockIdx.x;
    const int b  = bh >> 4, h = bh & 15;
    const int n0 = blockIdx.y * 64;
    const int tid = threadIdx.x;
    const int tx = tid & 15, ty = tid >> 4;

    // Load Q tile (64 rows x Dh=64)
    #pragma unroll
    for (int it = 0; it < 4; it++) {
        const int r = (tid >> 4) + it * 16;
        const int c = (tid & 15) * 4;
        float4 qv = *reinterpret_cast<const float4*>(
            qkv + (size_t)(b * NTOK + n0 + r) * (3 * C_) + h * DH_ + c);
        Qs[r][c + 0] = qv.x; Qs[r][c + 1] = qv.y;
        Qs[r][c + 2] = qv.z; Qs[r][c + 3] = qv.w;
    }

    float racc[4][16];   // [row i][chunk*4 + j]
    #pragma unroll
    for (int i = 0; i < 4; i++)
        #pragma unroll
        for (int e = 0; e < 16; e++) racc[i][e] = 0.0f;

    for (int m0 = 0; m0 < NTOK; m0 += 64) {
        __syncthreads();   // Ks safe to overwrite; also covers initial Q load
        #pragma unroll
        for (int it = 0; it < 4; it++) {
            const int r = (tid >> 4) + it * 16;
            const int c = (tid & 15) * 4;
            float4 kv = *reinterpret_cast<const float4*>(
                qkv + (size_t)(b * NTOK + m0 + r) * (3 * C_) + C_ + h * DH_ + c);
            Ks[r][c + 0] = kv.x; Ks[r][c + 1] = kv.y;
            Ks[r][c + 2] = kv.z; Ks[r][c + 3] = kv.w;
        }
        __syncthreads();

        const int ch = (m0 >> 6) * 4;
        #pragma unroll 8
        for (int kk = 0; kk < 64; kk++) {
            float ar[4], br[4];
            #pragma unroll
            for (int i = 0; i < 4; i++) ar[i] = Qs[ty * 4 + i][kk];
            #pragma unroll
            for (int j = 0; j < 4; j++) br[j] = Ks[tx * 4 + j][kk];
            #pragma unroll
            for (int i = 0; i < 4; i++)
                #pragma unroll
                for (int j = 0; j < 4; j++)
                    racc[i][ch + j] = fmaf(ar[i], br[j], racc[i][ch + j]);
        }
    }

    // bias + softmax per row (16 lanes per row, within one warp half)
    #pragma unroll
    for (int i = 0; i < 4; i++) {
        const int n = n0 + ty * 4 + i;
        float vals[16];
        float vmax = -1e30f;
        #pragma unroll
        for (int chunk = 0; chunk < 4; chunk++)
            #pragma unroll
            for (int j = 0; j < 4; j++) {
                const int m = chunk * 64 + tx * 4 + j;
                const float bb = rel_bias[rel_idx[n * NTOK + m] * H_ + h];
                float v = racc[i][chunk * 4 + j] * 0.125f + bb;
                vals[chunk * 4 + j] = v;
                vmax = fmaxf(vmax, v);
            }
        #pragma unroll
        for (int o = 8; o >= 1; o >>= 1)
            vmax = fmaxf(vmax, __shfl_xor_sync(0xffffffffu, vmax, o, 32));
        float ssum = 0.0f;
        #pragma unroll
        for (int e = 0; e < 16; e++) {
            vals[e] = __expf(vals[e] - vmax);
            ssum += vals[e];
        }
        #pragma unroll
        for (int o = 8; o >= 1; o >>= 1)
            ssum += __shfl_xor_sync(0xffffffffu, ssum, o, 32);
        const float inv = 1.0f / ssum;
        #pragma unroll
        for (int chunk = 0; chunk < 4; chunk++) {
            float4 o4;
            o4.x = vals[chunk * 4 + 0] * inv;
            o4.y = vals[chunk * 4 + 1] * inv;
            o4.z = vals[chunk * 4 + 2] * inv;
            o4.w = vals[chunk * 4 + 3] * inv;
            *reinterpret_cast<float4*>(
                P + ((size_t)bh * NTOK + n) * NTOK + chunk * 64 + tx * 4) = o4;
        }
    }
}

// ---------------------------------------------------------------------------
// PV: out[token, h*64+d] = sum_m P[bh,n,m] * V[bh,m,d]  (unchanged)
// ---------------------------------------------------------------------------
__global__ __launch_bounds__(256) void pv_kernel(
    const float* __restrict__ S, const float* __restrict__ qkv,
    float* __restrict__ attn_out)
{
    __shared__ float Ps[64][65];
    __shared__ float Vs[64][65];

    const int bh = blockIdx.x;
    const int b  = bh >> 4, h = bh & 15;
    const int n0 = blockIdx.y * 64;
    const int tid = threadIdx.x;
    const int tx = tid & 15, ty = tid >> 4;

    float acc[4][4] = {};

    for (int m0 = 0; m0 < NTOK; m0 += 64) {
        #pragma unroll
        for (int it = 0; it < 4; it++) {
            const int r = (tid >> 4) + it * 16;
            const int c = (tid & 15) * 4;
            float4 pv = *reinterpret_cast<const float4*>(
                S + ((size_t)bh * NTOK + n0 + r) * NTOK + m0 + c);
            Ps[r][c + 0] = pv.x; Ps[r][c + 1] = pv.y;
            Ps[r][c + 2] = pv.z; Ps[r][c + 3] = pv.w;
            float4 vv = *reinterpret_cast<const float4*>(
                qkv + (size_t)(b * NTOK + m0 + r) * (3 * C_) + 2 * C_ + h * DH_ + c);
            Vs[r][c + 0] = vv.x; Vs[r][c + 1] = vv.y;
            Vs[r][c + 2] = vv.z; Vs[r][c + 3] = vv.w;
        }
        __syncthreads();

        #pragma unroll 8
        for (int mm = 0; mm < 64; mm++) {
            float ar[4], br[4];
            #pragma unroll
            for (int i = 0; i < 4; i++) ar[i] = Ps[ty * 4 + i][mm];
            #pragma unroll
            for (int j = 0; j < 4; j++) br[j] = Vs[mm][tx * 4 + j];
            #pragma unroll
            for (int i = 0; i < 4; i++)
                #pragma unroll
                for (int j = 0; j < 4; j++)
                    acc[i][j] = fmaf(ar[i], br[j], acc[i][j]);
        }
        __syncthreads();
    }

    #pragma unroll
    for (int i = 0; i < 4; i++) {
        const int n = n0 + ty * 4 + i;
        #pragma unroll
        for (int j = 0; j < 4; j++) {
            const int d = tx * 4 + j;
            attn_out[(size_t)(b * NTOK + n) * C_ + h * DH_ + d] = acc[i][j];
        }
    }
}

// ---------------------------------------------------------------------------
// Launch
// ---------------------------------------------------------------------------
extern "C" void kernel_launch(void* const* d_in, const int* in_sizes, int n_in,
                              void* d_out, int out_size)
{
    const float* x        = (const float*)d_in[0];
    const int*   rel_idx  = (const int*)  d_in[1];
    const float* qkv_w    = (const float*)d_in[2];
    const float* qkv_b    = (const float*)d_in[3];
    const float* proj_w   = (const float*)d_in[4];
    const float* proj_b   = (const float*)d_in[5];
    const float* rel_bias = (const float*)d_in[6];
    const float* ln1_g    = (const float*)d_in[7];
    const float* ln1_b    = (const float*)d_in[8];
    const float* ln2_g    = (const float*)d_in[9];
    const float* ln2_b    = (const float*)d_in[10];
    const float* fc1_w    = (const float*)d_in[11];
    const float* fc1_b    = (const float*)d_in[12];
    const float* fc2_w    = (const float*)d_in[13];
    const float* fc2_b    = (const float*)d_in[14];
    float* out = (float*)d_out;

    float *ln, *qkv, *S, *attn, *x1, *ff;
    cudaGetSymbolAddress((void**)&ln,   g_ln);
    cudaGetSymbolAddress((void**)&qkv,  g_qkv);
    cudaGetSymbolAddress((void**)&S,    g_S);
    cudaGetSymbolAddress((void**)&attn, g_attn);
    cudaGetSymbolAddress((void**)&x1,   g_x1);
    cudaGetSymbolAddress((void**)&ff,   g_ff);

    // 1) LN1
    ln_kernel<<<MTOK, 256>>>(x, ln1_g, ln1_b, ln);
    // 2) QKV GEMM (tf32 tensor cores)
    wgemm128<EPI_BIAS><<<dim3(3 * C_ / 128, MTOK / 128), 256>>>(
        ln, qkv_w, qkv_b, nullptr, qkv, MTOK, 3 * C_, C_);
    // 3) fused scores + bias + softmax -> P
    scores_softmax_kernel<<<dim3(B_ * H_, NTOK / 64), 256>>>(
        qkv, rel_idx, rel_bias, S);
    // 4) P @ V, merge heads
    pv_kernel<<<dim3(B_ * H_, NTOK / 64), 256>>>(S, qkv, attn);
    // 5) proj + residual(x)
    wgemm128<EPI_RES><<<dim3(C_ / 128, MTOK / 128), 256>>>(
        attn, proj_w, proj_b, x, x1, MTOK, C_, C_);
    // 6) LN2
    ln_kernel<<<MTOK, 256>>>(x1, ln2_g, ln2_b, ln);
    // 7) FC1 + GELU
    wgemm128<EPI_GELU><<<dim3(DFF_ / 128, MTOK / 128), 256>>>(
        ln, fc1_w, fc1_b, nullptr, ff, MTOK, DFF_, C_);
    // 8) FC2 + residual(x1) -> out
    wgemm128<EPI_RES><<<dim3(C_ / 128, MTOK / 128), 256>>>(
        ff, fc2_w, fc2_b, x1, out, MTOK, C_, DFF_);
}

// round 5
// speedup vs baseline: 1.5040x; 1.0790x over previous
#include <cuda_runtime.h>
#include <math.h>
#include <mma.h>

using namespace nvcuda;

// Problem constants
#define B_     64
#define NTOK   256
#define C_     1024
#define H_     16
#define DH_    64
#define DFF_   4096
#define MTOK   (B_*NTOK)          // 16384 tokens
#define EPS_   1e-5f

// ---------------------------------------------------------------------------
// Scratch
// ---------------------------------------------------------------------------
__device__ float g_ln  [(size_t)MTOK * C_];
__device__ float g_qkv [(size_t)MTOK * 3 * C_];
__device__ float g_S   [(size_t)B_ * H_ * NTOK * NTOK];   // softmax probs P
__device__ float g_attn[(size_t)MTOK * C_];
__device__ float g_x1  [(size_t)MTOK * C_];
__device__ float g_ff  [(size_t)MTOK * DFF_];

// ---------------------------------------------------------------------------
// LayerNorm (unchanged, known-correct)
// ---------------------------------------------------------------------------
__global__ __launch_bounds__(256) void ln_kernel(
    const float* __restrict__ x, const float* __restrict__ g,
    const float* __restrict__ b, float* __restrict__ out)
{
    const int t   = blockIdx.x;
    const int tid = threadIdx.x;
    const float4 v = reinterpret_cast<const float4*>(x + (size_t)t * C_)[tid];

    float s  = v.x + v.y + v.z + v.w;
    float ss = v.x*v.x + v.y*v.y + v.z*v.z + v.w*v.w;

    __shared__ float rs[256], rq[256];
    rs[tid] = s; rq[tid] = ss;
    __syncthreads();
    #pragma unroll
    for (int o = 128; o > 0; o >>= 1) {
        if (tid < o) { rs[tid] += rs[tid + o]; rq[tid] += rq[tid + o]; }
        __syncthreads();
    }
    const float mu  = rs[0] * (1.0f / C_);
    const float var = rq[0] * (1.0f / C_) - mu * mu;
    const float inv = rsqrtf(var + EPS_);

    const float4 gv = reinterpret_cast<const float4*>(g)[tid];
    const float4 bv = reinterpret_cast<const float4*>(b)[tid];
    float4 o4;
    o4.x = (v.x - mu) * inv * gv.x + bv.x;
    o4.y = (v.y - mu) * inv * gv.y + bv.y;
    o4.z = (v.z - mu) * inv * gv.z + bv.z;
    o4.w = (v.w - mu) * inv * gv.w + bv.w;
    reinterpret_cast<float4*>(out + (size_t)t * C_)[tid] = o4;
}

// ---------------------------------------------------------------------------
// TF32 WMMA GEMM, 2-stage smem pipeline.
// 128x128 block tile, BK=16, 256 threads = 8 warps (2x4), 64x32 per warp.
// ---------------------------------------------------------------------------
enum { EPI_BIAS = 0, EPI_GELU = 1, EPI_RES = 2 };

__device__ __forceinline__ float gelu_tanh(float x) {
    const float k0 = 0.7978845608028654f;   // sqrt(2/pi)
    float x3 = x * x * x;
    return 0.5f * x * (1.0f + tanhf(k0 * (x + 0.044715f * x3)));
}

#define LDA_S 28   // As row stride: 112B (16B-mult); start banks -4r mod 32 -> 2-way max
#define LDB_S 132  // Bs row stride: 528B (16B-mult); start banks 4r mod 32 -> conflict-free
#define LDC_S 40   // epilogue stage row stride

__device__ __forceinline__ float4 to_tf32_4(float4 v) {
    float4 r;
    r.x = wmma::__float_to_tf32(v.x); r.y = wmma::__float_to_tf32(v.y);
    r.z = wmma::__float_to_tf32(v.z); r.w = wmma::__float_to_tf32(v.w);
    return r;
}

template <int EPI>
__global__ __launch_bounds__(256, 2) void wgemm128(
    const float* __restrict__ A, const float* __restrict__ W,
    const float* __restrict__ bias, const float* __restrict__ res,
    float* __restrict__ out, int M, int N, int K)
{
    __shared__ union SMem {
        struct {
            float As[2][128][LDA_S];   // [stage][m][k]
            float Bs[2][16][LDB_S];    // [stage][k][n]
        } p;
        float Cst[8][16][LDC_S];       // epilogue stage (aliases pipeline bufs)
    } sm;

    const int tid  = threadIdx.x;
    const int wid  = tid >> 5;
    const int lane = tid & 31;
    const int warp_m = wid & 1;       // 0..1 -> 64-row slab
    const int warp_n = wid >> 1;      // 0..3 -> 32-col slab
    const int row0 = blockIdx.y * 128;
    const int col0 = blockIdx.x * 128;

    // A loader: row = tid>>1 (0..127), col = (tid&1)*8
    const int arow = tid >> 1;
    const int acol = (tid & 1) * 8;
    const float* Ap = A + (size_t)(row0 + arow) * K + acol;
    // B loader: row = tid>>4 (0..15), col = (tid&15)*8
    const int brow = tid >> 4;
    const int bcol = (tid & 15) * 8;
    const float* Wp = W + (size_t)brow * N + col0 + bcol;

    wmma::fragment<wmma::accumulator, 16, 16, 8, float> c[4][2];
    #pragma unroll
    for (int mi = 0; mi < 4; mi++)
        #pragma unroll
        for (int nj = 0; nj < 2; nj++)
            wmma::fill_fragment(c[mi][nj], 0.0f);

    // ---- prologue: tile 0 -> stage 0
    {
        float4 a0 = to_tf32_4(*reinterpret_cast<const float4*>(Ap));
        float4 a1 = to_tf32_4(*reinterpret_cast<const float4*>(Ap + 4));
        float4 b0 = to_tf32_4(*reinterpret_cast<const float4*>(Wp));
        float4 b1 = to_tf32_4(*reinterpret_cast<const float4*>(Wp + 4));
        *reinterpret_cast<float4*>(&sm.p.As[0][arow][acol])     = a0;
        *reinterpret_cast<float4*>(&sm.p.As[0][arow][acol + 4]) = a1;
        *reinterpret_cast<float4*>(&sm.p.Bs[0][brow][bcol])     = b0;
        *reinterpret_cast<float4*>(&sm.p.Bs[0][brow][bcol + 4]) = b1;
    }
    __syncthreads();

    int stage = 0;
    for (int k0 = 0; k0 < K; k0 += 16) {
        const bool has_next = (k0 + 16) < K;
        float4 na0, na1, nb0, nb1;
        if (has_next) {
            // prefetch next tile global -> regs (overlaps with MMA below)
            na0 = *reinterpret_cast<const float4*>(Ap + k0 + 16);
            na1 = *reinterpret_cast<const float4*>(Ap + k0 + 16 + 4);
            nb0 = *reinterpret_cast<const float4*>(Wp + (size_t)(k0 + 16) * N);
            nb1 = *reinterpret_cast<const float4*>(Wp + (size_t)(k0 + 16) * N + 4);
        }

        #pragma unroll
        for (int kk = 0; kk < 16; kk += 8) {
            wmma::fragment<wmma::matrix_a, 16, 16, 8, wmma::precision::tf32, wmma::row_major> af[4];
            wmma::fragment<wmma::matrix_b, 16, 16, 8, wmma::precision::tf32, wmma::row_major> bf[2];
            #pragma unroll
            for (int mi = 0; mi < 4; mi++)
                wmma::load_matrix_sync(af[mi], &sm.p.As[stage][warp_m * 64 + mi * 16][kk], LDA_S);
            #pragma unroll
            for (int nj = 0; nj < 2; nj++)
                wmma::load_matrix_sync(bf[nj], &sm.p.Bs[stage][kk][warp_n * 32 + nj * 16], LDB_S);
            #pragma unroll
            for (int mi = 0; mi < 4; mi++)
                #pragma unroll
                for (int nj = 0; nj < 2; nj++)
                    wmma::mma_sync(c[mi][nj], af[mi], bf[nj], c[mi][nj]);
        }

        if (has_next) {
            const int ns = stage ^ 1;
            *reinterpret_cast<float4*>(&sm.p.As[ns][arow][acol])     = to_tf32_4(na0);
            *reinterpret_cast<float4*>(&sm.p.As[ns][arow][acol + 4]) = to_tf32_4(na1);
            *reinterpret_cast<float4*>(&sm.p.Bs[ns][brow][bcol])     = to_tf32_4(nb0);
            *reinterpret_cast<float4*>(&sm.p.Bs[ns][brow][bcol + 4]) = to_tf32_4(nb1);
        }
        __syncthreads();
        stage ^= 1;
    }

    // ---- epilogue: stage each 16x32 slab to smem, coalesced global writes
    // (mainloop's final __syncthreads orders all smem reads before this aliasing write)
    const int cg = col0 + warp_n * 32 + lane;       // this lane's global col
    const float bv = bias[cg];
    #pragma unroll
    for (int mi = 0; mi < 4; mi++) {
        wmma::store_matrix_sync(&sm.Cst[wid][0][0],  c[mi][0], LDC_S, wmma::mem_row_major);
        wmma::store_matrix_sync(&sm.Cst[wid][0][16], c[mi][1], LDC_S, wmma::mem_row_major);
        __syncwarp();
        const int rg0 = row0 + warp_m * 64 + mi * 16;
        #pragma unroll
        for (int rr = 0; rr < 16; rr++) {
            const int rg = rg0 + rr;
            float v = sm.Cst[wid][rr][lane] + bv;
            if (EPI == EPI_GELU) v = gelu_tanh(v);
            if (EPI == EPI_RES)  v += res[(size_t)rg * N + cg];
            out[(size_t)rg * N + cg] = v;
        }
        __syncwarp();
    }
}

// ---------------------------------------------------------------------------
// Fused scores + relpos bias + softmax (unchanged, known-correct)
// ---------------------------------------------------------------------------
__global__ __launch_bounds__(256) void scores_softmax_kernel(
    const float* __restrict__ qkv, const int* __restrict__ rel_idx,
    const float* __restrict__ rel_bias, float* __restrict__ P)
{
    __shared__ float Qs[64][65];
    __shared__ float Ks[64][65];

    const int bh = blockIdx.x;
    const int b  = bh >> 4, h = bh & 15;
    const int n0 = blockIdx.y * 64;
    const int tid = threadIdx.x;
    const int tx = tid & 15, ty = tid >> 4;

    #pragma unroll
    for (int it = 0; it < 4; it++) {
        const int r = (tid >> 4) + it * 16;
        const int c = (tid & 15) * 4;
        float4 qv = *reinterpret_cast<const float4*>(
            qkv + (size_t)(b * NTOK + n0 + r) * (3 * C_) + h * DH_ + c);
        Qs[r][c + 0] = qv.x; Qs[r][c + 1] = qv.y;
        Qs[r][c + 2] = qv.z; Qs[r][c + 3] = qv.w;
    }

    float racc[4][16];   // [row i][chunk*4 + j]
    #pragma unroll
    for (int i = 0; i < 4; i++)
        #pragma unroll
        for (int e = 0; e < 16; e++) racc[i][e] = 0.0f;

    for (int m0 = 0; m0 < NTOK; m0 += 64) {
        __syncthreads();
        #pragma unroll
        for (int it = 0; it < 4; it++) {
            const int r = (tid >> 4) + it * 16;
            const int c = (tid & 15) * 4;
            float4 kv = *reinterpret_cast<const float4*>(
                qkv + (size_t)(b * NTOK + m0 + r) * (3 * C_) + C_ + h * DH_ + c);
            Ks[r][c + 0] = kv.x; Ks[r][c + 1] = kv.y;
            Ks[r][c + 2] = kv.z; Ks[r][c + 3] = kv.w;
        }
        __syncthreads();

        const int ch = (m0 >> 6) * 4;
        #pragma unroll 8
        for (int kk = 0; kk < 64; kk++) {
            float ar[4], br[4];
            #pragma unroll
            for (int i = 0; i < 4; i++) ar[i] = Qs[ty * 4 + i][kk];
            #pragma unroll
            for (int j = 0; j < 4; j++) br[j] = Ks[tx * 4 + j][kk];
            #pragma unroll
            for (int i = 0; i < 4; i++)
                #pragma unroll
                for (int j = 0; j < 4; j++)
                    racc[i][ch + j] = fmaf(ar[i], br[j], racc[i][ch + j]);
        }
    }

    #pragma unroll
    for (int i = 0; i < 4; i++) {
        const int n = n0 + ty * 4 + i;
        float vals[16];
        float vmax = -1e30f;
        #pragma unroll
        for (int chunk = 0; chunk < 4; chunk++)
            #pragma unroll
            for (int j = 0; j < 4; j++) {
                const int m = chunk * 64 + tx * 4 + j;
                const float bb = rel_bias[rel_idx[n * NTOK + m] * H_ + h];
                float v = racc[i][chunk * 4 + j] * 0.125f + bb;
                vals[chunk * 4 + j] = v;
                vmax = fmaxf(vmax, v);
            }
        #pragma unroll
        for (int o = 8; o >= 1; o >>= 1)
            vmax = fmaxf(vmax, __shfl_xor_sync(0xffffffffu, vmax, o, 32));
        float ssum = 0.0f;
        #pragma unroll
        for (int e = 0; e < 16; e++) {
            vals[e] = __expf(vals[e] - vmax);
            ssum += vals[e];
        }
        #pragma unroll
        for (int o = 8; o >= 1; o >>= 1)
            ssum += __shfl_xor_sync(0xffffffffu, ssum, o, 32);
        const float inv = 1.0f / ssum;
        #pragma unroll
        for (int chunk = 0; chunk < 4; chunk++) {
            float4 o4;
            o4.x = vals[chunk * 4 + 0] * inv;
            o4.y = vals[chunk * 4 + 1] * inv;
            o4.z = vals[chunk * 4 + 2] * inv;
            o4.w = vals[chunk * 4 + 3] * inv;
            *reinterpret_cast<float4*>(
                P + ((size_t)bh * NTOK + n) * NTOK + chunk * 64 + tx * 4) = o4;
        }
    }
}

// ---------------------------------------------------------------------------
// PV: out[token, h*64+d] = sum_m P[bh,n,m] * V[bh,m,d]  (unchanged)
// ---------------------------------------------------------------------------
__global__ __launch_bounds__(256) void pv_kernel(
    const float* __restrict__ S, const float* __restrict__ qkv,
    float* __restrict__ attn_out)
{
    __shared__ float Ps[64][65];
    __shared__ float Vs[64][65];

    const int bh = blockIdx.x;
    const int b  = bh >> 4, h = bh & 15;
    const int n0 = blockIdx.y * 64;
    const int tid = threadIdx.x;
    const int tx = tid & 15, ty = tid >> 4;

    float acc[4][4] = {};

    for (int m0 = 0; m0 < NTOK; m0 += 64) {
        #pragma unroll
        for (int it = 0; it < 4; it++) {
            const int r = (tid >> 4) + it * 16;
            const int c = (tid & 15) * 4;
            float4 pv = *reinterpret_cast<const float4*>(
                S + ((size_t)bh * NTOK + n0 + r) * NTOK + m0 + c);
            Ps[r][c + 0] = pv.x; Ps[r][c + 1] = pv.y;
            Ps[r][c + 2] = pv.z; Ps[r][c + 3] = pv.w;
            float4 vv = *reinterpret_cast<const float4*>(
                qkv + (size_t)(b * NTOK + m0 + r) * (3 * C_) + 2 * C_ + h * DH_ + c);
            Vs[r][c + 0] = vv.x; Vs[r][c + 1] = vv.y;
            Vs[r][c + 2] = vv.z; Vs[r][c + 3] = vv.w;
        }
        __syncthreads();

        #pragma unroll 8
        for (int mm = 0; mm < 64; mm++) {
            float ar[4], br[4];
            #pragma unroll
            for (int i = 0; i < 4; i++) ar[i] = Ps[ty * 4 + i][mm];
            #pragma unroll
            for (int j = 0; j < 4; j++) br[j] = Vs[mm][tx * 4 + j];
            #pragma unroll
            for (int i = 0; i < 4; i++)
                #pragma unroll
                for (int j = 0; j < 4; j++)
                    acc[i][j] = fmaf(ar[i], br[j], acc[i][j]);
        }
        __syncthreads();
    }

    #pragma unroll
    for (int i = 0; i < 4; i++) {
        const int n = n0 + ty * 4 + i;
        #pragma unroll
        for (int j = 0; j < 4; j++) {
            const int d = tx * 4 + j;
            attn_out[(size_t)(b * NTOK + n) * C_ + h * DH_ + d] = acc[i][j];
        }
    }
}

// ---------------------------------------------------------------------------
// Launch
// ---------------------------------------------------------------------------
extern "C" void kernel_launch(void* const* d_in, const int* in_sizes, int n_in,
                              void* d_out, int out_size)
{
    const float* x        = (const float*)d_in[0];
    const int*   rel_idx  = (const int*)  d_in[1];
    const float* qkv_w    = (const float*)d_in[2];
    const float* qkv_b    = (const float*)d_in[3];
    const float* proj_w   = (const float*)d_in[4];
    const float* proj_b   = (const float*)d_in[5];
    const float* rel_bias = (const float*)d_in[6];
    const float* ln1_g    = (const float*)d_in[7];
    const float* ln1_b    = (const float*)d_in[8];
    const float* ln2_g    = (const float*)d_in[9];
    const float* ln2_b    = (const float*)d_in[10];
    const float* fc1_w    = (const float*)d_in[11];
    const float* fc1_b    = (const float*)d_in[12];
    const float* fc2_w    = (const float*)d_in[13];
    const float* fc2_b    = (const float*)d_in[14];
    float* out = (float*)d_out;

    float *ln, *qkv, *S, *attn, *x1, *ff;
    cudaGetSymbolAddress((void**)&ln,   g_ln);
    cudaGetSymbolAddress((void**)&qkv,  g_qkv);
    cudaGetSymbolAddress((void**)&S,    g_S);
    cudaGetSymbolAddress((void**)&attn, g_attn);
    cudaGetSymbolAddress((void**)&x1,   g_x1);
    cudaGetSymbolAddress((void**)&ff,   g_ff);

    // 1) LN1
    ln_kernel<<<MTOK, 256>>>(x, ln1_g, ln1_b, ln);
    // 2) QKV GEMM (tf32 tensor cores, pipelined)
    wgemm128<EPI_BIAS><<<dim3(3 * C_ / 128, MTOK / 128), 256>>>(
        ln, qkv_w, qkv_b, nullptr, qkv, MTOK, 3 * C_, C_);
    // 3) fused scores + bias + softmax -> P
    scores_softmax_kernel<<<dim3(B_ * H_, NTOK / 64), 256>>>(
        qkv, rel_idx, rel_bias, S);
    // 4) P @ V, merge heads
    pv_kernel<<<dim3(B_ * H_, NTOK / 64), 256>>>(S, qkv, attn);
    // 5) proj + residual(x)
    wgemm128<EPI_RES><<<dim3(C_ / 128, MTOK / 128), 256>>>(
        attn, proj_w, proj_b, x, x1, MTOK, C_, C_);
    // 6) LN2
    ln_kernel<<<MTOK, 256>>>(x1, ln2_g, ln2_b, ln);
    // 7) FC1 + GELU
    wgemm128<EPI_GELU><<<dim3(DFF_ / 128, MTOK / 128), 256>>>(
        ln, fc1_w, fc1_b, nullptr, ff, MTOK, DFF_, C_);
    // 8) FC2 + residual(x1) -> out
    wgemm128<EPI_RES><<<dim3(C_ / 128, MTOK / 128), 256>>>(
        ff, fc2_w, fc2_b, x1, out, MTOK, C_, DFF_);
}

// round 9
// speedup vs baseline: 4.0665x; 2.7038x over previous
#include <cuda_runtime.h>
#include <cuda_fp16.h>
#include <math.h>
#include <stdint.h>
#include <mma.h>

using namespace nvcuda;

// Problem constants
#define B_     64
#define NTOK   256
#define C_     1024
#define H_     16
#define DH_    64
#define DFF_   4096
#define MTOK   (B_*NTOK)          // 16384 tokens
#define EPS_   1e-5f

// ---------------------------------------------------------------------------
// Scratch
// ---------------------------------------------------------------------------
__device__ __half g_lnh [(size_t)MTOK * C_];        //  32 MB LN output (fp16)
__device__ float  g_qkv [(size_t)MTOK * 3 * C_];    // 192 MB
__device__ float  g_S   [(size_t)B_ * H_ * NTOK * NTOK]; // 268 MB probs
__device__ __half g_attnh[(size_t)MTOK * C_];       //  32 MB merged attn (fp16)
__device__ float  g_x1  [(size_t)MTOK * C_];        //  64 MB post-attn residual
__device__ __half g_ffh [(size_t)MTOK * DFF_];      // 128 MB MLP hidden (fp16)
__device__ __half g_wh  [(size_t)12 * 1024 * 1024]; //  24 MB fp16 weights

// ---------------------------------------------------------------------------
// cp.async helpers
// ---------------------------------------------------------------------------
__device__ __forceinline__ uint32_t smem_u32(const void* p) {
    uint32_t a;
    asm("{ .reg .u64 t; cvta.to.shared.u64 t, %1; cvt.u32.u64 %0, t; }"
        : "=r"(a) : "l"(p));
    return a;
}
#define CP_ASYNC16(dst, src) \
    asm volatile("cp.async.cg.shared.global [%0], [%1], 16;" :: "r"(dst), "l"(src))
#define CP_COMMIT() asm volatile("cp.async.commit_group;" ::: "memory")
#define CP_WAIT0()  asm volatile("cp.async.wait_group 0;" ::: "memory")

// ---------------------------------------------------------------------------
// fp32 -> fp16 weight conversion
// ---------------------------------------------------------------------------
__global__ __launch_bounds__(256) void f2h_kernel(
    const float* __restrict__ src, __half* __restrict__ dst, int n4)
{
    const int i = blockIdx.x * 256 + threadIdx.x;
    if (i < n4) {
        const float4 v = reinterpret_cast<const float4*>(src)[i];
        __half2 h0 = __floats2half2_rn(v.x, v.y);
        __half2 h1 = __floats2half2_rn(v.z, v.w);
        reinterpret_cast<__half2*>(dst)[i * 2 + 0] = h0;
        reinterpret_cast<__half2*>(dst)[i * 2 + 1] = h1;
    }
}

// ---------------------------------------------------------------------------
// LayerNorm: fp32 in, fp16 out (output only feeds GEMM A operands)
// ---------------------------------------------------------------------------
__global__ __launch_bounds__(256) void ln_kernel(
    const float* __restrict__ x, const float* __restrict__ g,
    const float* __restrict__ b, __half* __restrict__ out)
{
    const int t   = blockIdx.x;
    const int tid = threadIdx.x;
    const float4 v = reinterpret_cast<const float4*>(x + (size_t)t * C_)[tid];

    float s  = v.x + v.y + v.z + v.w;
    float ss = v.x*v.x + v.y*v.y + v.z*v.z + v.w*v.w;

    __shared__ float rs[256], rq[256];
    rs[tid] = s; rq[tid] = ss;
    __syncthreads();
    #pragma unroll
    for (int o = 128; o > 0; o >>= 1) {
        if (tid < o) { rs[tid] += rs[tid + o]; rq[tid] += rq[tid + o]; }
        __syncthreads();
    }
    const float mu  = rs[0] * (1.0f / C_);
    const float var = rq[0] * (1.0f / C_) - mu * mu;
    const float inv = rsqrtf(var + EPS_);

    const float4 gv = reinterpret_cast<const float4*>(g)[tid];
    const float4 bv = reinterpret_cast<const float4*>(b)[tid];
    __half2 h0 = __floats2half2_rn((v.x - mu) * inv * gv.x + bv.x,
                                   (v.y - mu) * inv * gv.y + bv.y);
    __half2 h1 = __floats2half2_rn((v.z - mu) * inv * gv.z + bv.z,
                                   (v.w - mu) * inv * gv.w + bv.w);
    reinterpret_cast<__half2*>(out + (size_t)t * C_)[tid * 2 + 0] = h0;
    reinterpret_cast<__half2*>(out + (size_t)t * C_)[tid * 2 + 1] = h1;
}

// ---------------------------------------------------------------------------
// FP16 WMMA GEMM with cp.async double buffering.
// out[M,N] = A[M,K](fp16) @ W[K,N](fp16) + bias (+gelu->fp16 | +res->fp32)
// 128x128 tile, BK=32, 256 threads = 8 warps (2x4), 64x32 per warp.
// ---------------------------------------------------------------------------
enum { EPI_BIAS = 0, EPI_GELU = 1, EPI_RES = 2 };

__device__ __forceinline__ float gelu_tanh(float x) {
    const float k0 = 0.7978845608028654f;   // sqrt(2/pi)
    float x3 = x * x * x;
    return 0.5f * x * (1.0f + tanhf(k0 * (x + 0.044715f * x3)));
}

#define HLDA 40    // As row stride (halves): 80B; ldmatrix banks 20r%32 distinct
#define HLDB 136   // Bs row stride (halves): 272B; banks 4k%32 distinct
#define LDC_S 40

template <int EPI, typename OutT>
__global__ __launch_bounds__(256, 2) void hgemm(
    const __half* __restrict__ A, const __half* __restrict__ W,
    const float* __restrict__ bias, const float* __restrict__ res,
    OutT* __restrict__ out, int M, int N, int K)
{
    __shared__ union SMem {
        struct {
            __half As[2][128][HLDA];   // 2 x 10240 B
            __half Bs[2][32][HLDB];    // 2 x 8704 B
        } p;
        float Cst[8][16][LDC_S];       // epilogue stage (20 KB)
    } sm;

    const int tid  = threadIdx.x;
    const int wid  = tid >> 5;
    const int lane = tid & 31;
    const int warp_m = wid & 1;       // 64-row slab
    const int warp_n = wid >> 1;      // 32-col slab
    const int row0 = blockIdx.y * 128;
    const int col0 = blockIdx.x * 128;

    // A loader: thread -> row tid>>1, halves [(tid&1)*16, +16)
    const int arow = tid >> 1;
    const int acol = (tid & 1) * 16;
    const __half* Ap = A + (size_t)(row0 + arow) * K + acol;
    // B loader: thread -> k-row tid>>3, halves [(tid&7)*16, +16)
    const int brow = tid >> 3;
    const int bcol = (tid & 7) * 16;
    const __half* Wp = W + (size_t)brow * N + col0 + bcol;

    uint32_t uA[2], uB[2];
    #pragma unroll
    for (int s = 0; s < 2; s++) {
        uA[s] = smem_u32(&sm.p.As[s][arow][acol]);
        uB[s] = smem_u32(&sm.p.Bs[s][brow][bcol]);
    }

    wmma::fragment<wmma::accumulator, 16, 16, 16, float> c[4][2];
    #pragma unroll
    for (int mi = 0; mi < 4; mi++)
        #pragma unroll
        for (int nj = 0; nj < 2; nj++)
            wmma::fill_fragment(c[mi][nj], 0.0f);

    const int n_iter = K >> 5;   // BK = 32

    // prologue: stage 0
    CP_ASYNC16(uA[0],      Ap);
    CP_ASYNC16(uA[0] + 16, Ap + 8);
    CP_ASYNC16(uB[0],      Wp);
    CP_ASYNC16(uB[0] + 16, Wp + 8);
    CP_COMMIT();

    int st = 0;
    for (int it = 0; it < n_iter; ++it) {
        CP_WAIT0();
        __syncthreads();    // stage st ready for all; stage st^1 free for reuse

        if (it + 1 < n_iter) {
            const int koff = (it + 1) << 5;
            const int ns = st ^ 1;
            CP_ASYNC16(uA[ns],      Ap + koff);
            CP_ASYNC16(uA[ns] + 16, Ap + koff + 8);
            CP_ASYNC16(uB[ns],      Wp + (size_t)koff * N);
            CP_ASYNC16(uB[ns] + 16, Wp + (size_t)koff * N + 8);
            CP_COMMIT();
        }

        #pragma unroll
        for (int kk = 0; kk < 32; kk += 16) {
            wmma::fragment<wmma::matrix_b, 16, 16, 16, __half, wmma::row_major> bf[2];
            #pragma unroll
            for (int nj = 0; nj < 2; nj++)
                wmma::load_matrix_sync(bf[nj], &sm.p.Bs[st][kk][warp_n * 32 + nj * 16], HLDB);
            #pragma unroll
            for (int mi = 0; mi < 4; mi++) {
                wmma::fragment<wmma::matrix_a, 16, 16, 16, __half, wmma::row_major> af;
                wmma::load_matrix_sync(af, &sm.p.As[st][warp_m * 64 + mi * 16][kk], HLDA);
                #pragma unroll
                for (int nj = 0; nj < 2; nj++)
                    wmma::mma_sync(c[mi][nj], af, bf[nj], c[mi][nj]);
            }
        }
        st ^= 1;
    }
    __syncthreads();   // all compute done before Cst aliases pipeline buffers

    // Epilogue: stage 16x32 slabs, coalesced writes
    const int cg = col0 + warp_n * 32 + lane;
    const float bv = bias[cg];
    #pragma unroll
    for (int mi = 0; mi < 4; mi++) {
        wmma::store_matrix_sync(&sm.Cst[wid][0][0],  c[mi][0], LDC_S, wmma::mem_row_major);
        wmma::store_matrix_sync(&sm.Cst[wid][0][16], c[mi][1], LDC_S, wmma::mem_row_major);
        __syncwarp();
        const int rg0 = row0 + warp_m * 64 + mi * 16;
        #pragma unroll
        for (int rr = 0; rr < 16; rr++) {
            const int rg = rg0 + rr;
            float v = sm.Cst[wid][rr][lane] + bv;
            if (EPI == EPI_GELU) v = gelu_tanh(v);
            if (EPI == EPI_RES)  v += res[(size_t)rg * N + cg];
            if (sizeof(OutT) == 2)
                out[(size_t)rg * N + cg] = (OutT)__float2half(v);
            else
                out[(size_t)rg * N + cg] = (OutT)v;
        }
        __syncwarp();
    }
}

// ---------------------------------------------------------------------------
// Fused scores + relpos bias + softmax (unchanged, known-correct)
// ---------------------------------------------------------------------------
__global__ __launch_bounds__(256) void scores_softmax_kernel(
    const float* __restrict__ qkv, const int* __restrict__ rel_idx,
    const float* __restrict__ rel_bias, float* __restrict__ P)
{
    __shared__ float Qs[64][65];
    __shared__ float Ks[64][65];

    const int bh = blockIdx.x;
    const int b  = bh >> 4, h = bh & 15;
    const int n0 = blockIdx.y * 64;
    const int tid = threadIdx.x;
    const int tx = tid & 15, ty = tid >> 4;

    #pragma unroll
    for (int it = 0; it < 4; it++) {
        const int r = (tid >> 4) + it * 16;
        const int c = (tid & 15) * 4;
        float4 qv = *reinterpret_cast<const float4*>(
            qkv + (size_t)(b * NTOK + n0 + r) * (3 * C_) + h * DH_ + c);
        Qs[r][c + 0] = qv.x; Qs[r][c + 1] = qv.y;
        Qs[r][c + 2] = qv.z; Qs[r][c + 3] = qv.w;
    }

    float racc[4][16];
    #pragma unroll
    for (int i = 0; i < 4; i++)
        #pragma unroll
        for (int e = 0; e < 16; e++) racc[i][e] = 0.0f;

    for (int m0 = 0; m0 < NTOK; m0 += 64) {
        __syncthreads();
        #pragma unroll
        for (int it = 0; it < 4; it++) {
            const int r = (tid >> 4) + it * 16;
            const int c = (tid & 15) * 4;
            float4 kv = *reinterpret_cast<const float4*>(
                qkv + (size_t)(b * NTOK + m0 + r) * (3 * C_) + C_ + h * DH_ + c);
            Ks[r][c + 0] = kv.x; Ks[r][c + 1] = kv.y;
            Ks[r][c + 2] = kv.z; Ks[r][c + 3] = kv.w;
        }
        __syncthreads();

        const int ch = (m0 >> 6) * 4;
        #pragma unroll 8
        for (int kk = 0; kk < 64; kk++) {
            float ar[4], br[4];
            #pragma unroll
            for (int i = 0; i < 4; i++) ar[i] = Qs[ty * 4 + i][kk];
            #pragma unroll
            for (int j = 0; j < 4; j++) br[j] = Ks[tx * 4 + j][kk];
            #pragma unroll
            for (int i = 0; i < 4; i++)
                #pragma unroll
                for (int j = 0; j < 4; j++)
                    racc[i][ch + j] = fmaf(ar[i], br[j], racc[i][ch + j]);
        }
    }

    #pragma unroll
    for (int i = 0; i < 4; i++) {
        const int n = n0 + ty * 4 + i;
        float vals[16];
        float vmax = -1e30f;
        #pragma unroll
        for (int chunk = 0; chunk < 4; chunk++)
            #pragma unroll
            for (int j = 0; j < 4; j++) {
                const int m = chunk * 64 + tx * 4 + j;
                const float bb = rel_bias[rel_idx[n * NTOK + m] * H_ + h];
                float v = racc[i][chunk * 4 + j] * 0.125f + bb;
                vals[chunk * 4 + j] = v;
                vmax = fmaxf(vmax, v);
            }
        #pragma unroll
        for (int o = 8; o >= 1; o >>= 1)
            vmax = fmaxf(vmax, __shfl_xor_sync(0xffffffffu, vmax, o, 32));
        float ssum = 0.0f;
        #pragma unroll
        for (int e = 0; e < 16; e++) {
            vals[e] = __expf(vals[e] - vmax);
            ssum += vals[e];
        }
        #pragma unroll
        for (int o = 8; o >= 1; o >>= 1)
            ssum += __shfl_xor_sync(0xffffffffu, ssum, o, 32);
        const float inv = 1.0f / ssum;
        #pragma unroll
        for (int chunk = 0; chunk < 4; chunk++) {
            float4 o4;
            o4.x = vals[chunk * 4 + 0] * inv;
            o4.y = vals[chunk * 4 + 1] * inv;
            o4.z = vals[chunk * 4 + 2] * inv;
            o4.w = vals[chunk * 4 + 3] * inv;
            *reinterpret_cast<float4*>(
                P + ((size_t)bh * NTOK + n) * NTOK + chunk * 64 + tx * 4) = o4;
        }
    }
}

// ---------------------------------------------------------------------------
// PV: fp32 math, fp16 output (feeds proj GEMM)
// ---------------------------------------------------------------------------
__global__ __launch_bounds__(256) void pv_kernel(
    const float* __restrict__ S, const float* __restrict__ qkv,
    __half* __restrict__ attn_out)
{
    __shared__ float Ps[64][65];
    __shared__ float Vs[64][65];

    const int bh = blockIdx.x;
    const int b  = bh >> 4, h = bh & 15;
    const int n0 = blockIdx.y * 64;
    const int tid = threadIdx.x;
    const int tx = tid & 15, ty = tid >> 4;

    float acc[4][4] = {};

    for (int m0 = 0; m0 < NTOK; m0 += 64) {
        #pragma unroll
        for (int it = 0; it < 4; it++) {
            const int r = (tid >> 4) + it * 16;
            const int c = (tid & 15) * 4;
            float4 pv = *reinterpret_cast<const float4*>(
                S + ((size_t)bh * NTOK + n0 + r) * NTOK + m0 + c);
            Ps[r][c + 0] = pv.x; Ps[r][c + 1] = pv.y;
            Ps[r][c + 2] = pv.z; Ps[r][c + 3] = pv.w;
            float4 vv = *reinterpret_cast<const float4*>(
                qkv + (size_t)(b * NTOK + m0 + r) * (3 * C_) + 2 * C_ + h * DH_ + c);
            Vs[r][c + 0] = vv.x; Vs[r][c + 1] = vv.y;
            Vs[r][c + 2] = vv.z; Vs[r][c + 3] = vv.w;
        }
        __syncthreads();

        #pragma unroll 8
        for (int mm = 0; mm < 64; mm++) {
            float ar[4], br[4];
            #pragma unroll
            for (int i = 0; i < 4; i++) ar[i] = Ps[ty * 4 + i][mm];
            #pragma unroll
            for (int j = 0; j < 4; j++) br[j] = Vs[mm][tx * 4 + j];
            #pragma unroll
            for (int i = 0; i < 4; i++)
                #pragma unroll
                for (int j = 0; j < 4; j++)
                    acc[i][j] = fmaf(ar[i], br[j], acc[i][j]);
        }
        __syncthreads();
    }

    #pragma unroll
    for (int i = 0; i < 4; i++) {
        const int n = n0 + ty * 4 + i;
        #pragma unroll
        for (int j = 0; j < 4; j++) {
            const int d = tx * 4 + j;
            attn_out[(size_t)(b * NTOK + n) * C_ + h * DH_ + d] =
                __float2half(acc[i][j]);
        }
    }
}

// ---------------------------------------------------------------------------
// Launch
// ---------------------------------------------------------------------------
extern "C" void kernel_launch(void* const* d_in, const int* in_sizes, int n_in,
                              void* d_out, int out_size)
{
    const float* x        = (const float*)d_in[0];
    const int*   rel_idx  = (const int*)  d_in[1];
    const float* qkv_w    = (const float*)d_in[2];
    const float* qkv_b    = (const float*)d_in[3];
    const float* proj_w   = (const float*)d_in[4];
    const float* proj_b   = (const float*)d_in[5];
    const float* rel_bias = (const float*)d_in[6];
    const float* ln1_g    = (const float*)d_in[7];
    const float* ln1_b    = (const float*)d_in[8];
    const float* ln2_g    = (const float*)d_in[9];
    const float* ln2_b    = (const float*)d_in[10];
    const float* fc1_w    = (const float*)d_in[11];
    const float* fc1_b    = (const float*)d_in[12];
    const float* fc2_w    = (const float*)d_in[13];
    const float* fc2_b    = (const float*)d_in[14];
    float* out = (float*)d_out;

    __half *lnh, *attnh, *ffh, *wh;
    float *qkv, *S, *x1;
    cudaGetSymbolAddress((void**)&lnh,   g_lnh);
    cudaGetSymbolAddress((void**)&qkv,   g_qkv);
    cudaGetSymbolAddress((void**)&S,     g_S);
    cudaGetSymbolAddress((void**)&attnh, g_attnh);
    cudaGetSymbolAddress((void**)&x1,    g_x1);
    cudaGetSymbolAddress((void**)&ffh,   g_ffh);
    cudaGetSymbolAddress((void**)&wh,    g_wh);

    __half* qkv_wh = wh;                               // [1024,3072]
    __half* proj_wh = wh + (size_t)3 * 1024 * 1024;    // [1024,1024]
    __half* fc1_wh  = wh + (size_t)4 * 1024 * 1024;    // [1024,4096]
    __half* fc2_wh  = wh + (size_t)8 * 1024 * 1024;    // [4096,1024]

    // 0) fp16 weight conversion
    f2h_kernel<<<(3 * 1024 * 1024 / 4 + 255) / 256, 256>>>(qkv_w, qkv_wh, 3 * 1024 * 1024 / 4);
    f2h_kernel<<<(1024 * 1024 / 4 + 255) / 256, 256>>>(proj_w, proj_wh, 1024 * 1024 / 4);
    f2h_kernel<<<(4 * 1024 * 1024 / 4 + 255) / 256, 256>>>(fc1_w, fc1_wh, 4 * 1024 * 1024 / 4);
    f2h_kernel<<<(4 * 1024 * 1024 / 4 + 255) / 256, 256>>>(fc2_w, fc2_wh, 4 * 1024 * 1024 / 4);

    // 1) LN1 -> fp16
    ln_kernel<<<MTOK, 256>>>(x, ln1_g, ln1_b, lnh);
    // 2) QKV GEMM
    hgemm<EPI_BIAS, float><<<dim3(3 * C_ / 128, MTOK / 128), 256>>>(
        lnh, qkv_wh, qkv_b, nullptr, qkv, MTOK, 3 * C_, C_);
    // 3) fused scores + bias + softmax -> P
    scores_softmax_kernel<<<dim3(B_ * H_, NTOK / 64), 256>>>(
        qkv, rel_idx, rel_bias, S);
    // 4) P @ V -> fp16 merged heads
    pv_kernel<<<dim3(B_ * H_, NTOK / 64), 256>>>(S, qkv, attnh);
    // 5) proj + residual(x) -> x1 (fp32)
    hgemm<EPI_RES, float><<<dim3(C_ / 128, MTOK / 128), 256>>>(
        attnh, proj_wh, proj_b, x, x1, MTOK, C_, C_);
    // 6) LN2 -> fp16
    ln_kernel<<<MTOK, 256>>>(x1, ln2_g, ln2_b, lnh);
    // 7) FC1 + GELU -> fp16
    hgemm<EPI_GELU, __half><<<dim3(DFF_ / 128, MTOK / 128), 256>>>(
        lnh, fc1_wh, fc1_b, nullptr, ffh, MTOK, DFF_, C_);
    // 8) FC2 + residual(x1) -> out (fp32)
    hgemm<EPI_RES, float><<<dim3(C_ / 128, MTOK / 128), 256>>>(
        ffh, fc2_wh, fc2_b, x1, out, MTOK, C_, DFF_);
}

// round 10
// speedup vs baseline: 5.1714x; 1.2717x over previous
#include <cuda_runtime.h>
#include <cuda_fp16.h>
#include <math.h>
#include <stdint.h>
#include <mma.h>

using namespace nvcuda;

// Problem constants
#define B_     64
#define NTOK   256
#define C_     1024
#define H_     16
#define DH_    64
#define DFF_   4096
#define MTOK   (B_*NTOK)          // 16384 tokens
#define EPS_   1e-5f

// ---------------------------------------------------------------------------
// Scratch
// ---------------------------------------------------------------------------
__device__ __half g_lnh [(size_t)MTOK * C_];         //  32 MB LN out (fp16)
__device__ __half g_qkvh[(size_t)MTOK * 3 * C_];     //  96 MB qkv (fp16)
__device__ __half g_attnh[(size_t)MTOK * C_];        //  32 MB merged attn (fp16)
__device__ float  g_x1  [(size_t)MTOK * C_];         //  64 MB post-attn residual
__device__ __half g_ffh [(size_t)MTOK * DFF_];       // 128 MB MLP hidden (fp16)
__device__ __half g_wh  [(size_t)12 * 1024 * 1024];  //  24 MB fp16 weights
__device__ float  g_bias[(size_t)H_ * NTOK * NTOK];  //   4 MB gathered rel bias

// ---------------------------------------------------------------------------
// helpers
// ---------------------------------------------------------------------------
__device__ __forceinline__ uint32_t smem_u32(const void* p) {
    uint32_t a;
    asm("{ .reg .u64 t; cvta.to.shared.u64 t, %1; cvt.u32.u64 %0, t; }"
        : "=r"(a) : "l"(p));
    return a;
}
#define CP_ASYNC16(dst, src) \
    asm volatile("cp.async.cg.shared.global [%0], [%1], 16;" :: "r"(dst), "l"(src))
#define CP_COMMIT() asm volatile("cp.async.commit_group;" ::: "memory")
#define CP_WAIT0()  asm volatile("cp.async.wait_group 0;" ::: "memory")

__global__ __launch_bounds__(256) void f2h_kernel(
    const float* __restrict__ src, __half* __restrict__ dst, int n4)
{
    const int i = blockIdx.x * 256 + threadIdx.x;
    if (i < n4) {
        const float4 v = reinterpret_cast<const float4*>(src)[i];
        reinterpret_cast<__half2*>(dst)[i * 2 + 0] = __floats2half2_rn(v.x, v.y);
        reinterpret_cast<__half2*>(dst)[i * 2 + 1] = __floats2half2_rn(v.z, v.w);
    }
}

// gathered bias: bf[h][n*256+m] = rel_bias[rel_idx[n*256+m]*H + h]
__global__ __launch_bounds__(256) void bias_gather_kernel(
    const int* __restrict__ rel_idx, const float* __restrict__ rel_bias,
    float* __restrict__ bf)
{
    const int i = blockIdx.x * 256 + threadIdx.x;   // 0..65535
    const int h = blockIdx.y;
    bf[(size_t)h * (NTOK * NTOK) + i] = rel_bias[rel_idx[i] * H_ + h];
}

// ---------------------------------------------------------------------------
// LayerNorm: fp32 in, fp16 out
// ---------------------------------------------------------------------------
__global__ __launch_bounds__(256) void ln_kernel(
    const float* __restrict__ x, const float* __restrict__ g,
    const float* __restrict__ b, __half* __restrict__ out)
{
    const int t   = blockIdx.x;
    const int tid = threadIdx.x;
    const float4 v = reinterpret_cast<const float4*>(x + (size_t)t * C_)[tid];

    float s  = v.x + v.y + v.z + v.w;
    float ss = v.x*v.x + v.y*v.y + v.z*v.z + v.w*v.w;

    __shared__ float rs[256], rq[256];
    rs[tid] = s; rq[tid] = ss;
    __syncthreads();
    #pragma unroll
    for (int o = 128; o > 0; o >>= 1) {
        if (tid < o) { rs[tid] += rs[tid + o]; rq[tid] += rq[tid + o]; }
        __syncthreads();
    }
    const float mu  = rs[0] * (1.0f / C_);
    const float var = rq[0] * (1.0f / C_) - mu * mu;
    const float inv = rsqrtf(var + EPS_);

    const float4 gv = reinterpret_cast<const float4*>(g)[tid];
    const float4 bv = reinterpret_cast<const float4*>(b)[tid];
    __half2 h0 = __floats2half2_rn((v.x - mu) * inv * gv.x + bv.x,
                                   (v.y - mu) * inv * gv.y + bv.y);
    __half2 h1 = __floats2half2_rn((v.z - mu) * inv * gv.z + bv.z,
                                   (v.w - mu) * inv * gv.w + bv.w);
    reinterpret_cast<__half2*>(out + (size_t)t * C_)[tid * 2 + 0] = h0;
    reinterpret_cast<__half2*>(out + (size_t)t * C_)[tid * 2 + 1] = h1;
}

// ---------------------------------------------------------------------------
// FP16 WMMA GEMM with cp.async double buffering (R9, known-good).
// ---------------------------------------------------------------------------
enum { EPI_BIAS = 0, EPI_GELU = 1, EPI_RES = 2 };

__device__ __forceinline__ float gelu_tanh(float x) {
    const float k0 = 0.7978845608028654f;
    float x3 = x * x * x;
    return 0.5f * x * (1.0f + tanhf(k0 * (x + 0.044715f * x3)));
}

#define HLDA 40
#define HLDB 136
#define LDC_S 40

template <int EPI, typename OutT>
__global__ __launch_bounds__(256, 2) void hgemm(
    const __half* __restrict__ A, const __half* __restrict__ W,
    const float* __restrict__ bias, const float* __restrict__ res,
    OutT* __restrict__ out, int M, int N, int K)
{
    __shared__ union SMem {
        struct {
            __half As[2][128][HLDA];
            __half Bs[2][32][HLDB];
        } p;
        float Cst[8][16][LDC_S];
    } sm;

    const int tid  = threadIdx.x;
    const int wid  = tid >> 5;
    const int lane = tid & 31;
    const int warp_m = wid & 1;
    const int warp_n = wid >> 1;
    const int row0 = blockIdx.y * 128;
    const int col0 = blockIdx.x * 128;

    const int arow = tid >> 1;
    const int acol = (tid & 1) * 16;
    const __half* Ap = A + (size_t)(row0 + arow) * K + acol;
    const int brow = tid >> 3;
    const int bcol = (tid & 7) * 16;
    const __half* Wp = W + (size_t)brow * N + col0 + bcol;

    uint32_t uA[2], uB[2];
    #pragma unroll
    for (int s = 0; s < 2; s++) {
        uA[s] = smem_u32(&sm.p.As[s][arow][acol]);
        uB[s] = smem_u32(&sm.p.Bs[s][brow][bcol]);
    }

    wmma::fragment<wmma::accumulator, 16, 16, 16, float> c[4][2];
    #pragma unroll
    for (int mi = 0; mi < 4; mi++)
        #pragma unroll
        for (int nj = 0; nj < 2; nj++)
            wmma::fill_fragment(c[mi][nj], 0.0f);

    const int n_iter = K >> 5;

    CP_ASYNC16(uA[0],      Ap);
    CP_ASYNC16(uA[0] + 16, Ap + 8);
    CP_ASYNC16(uB[0],      Wp);
    CP_ASYNC16(uB[0] + 16, Wp + 8);
    CP_COMMIT();

    int st = 0;
    for (int it = 0; it < n_iter; ++it) {
        CP_WAIT0();
        __syncthreads();

        if (it + 1 < n_iter) {
            const int koff = (it + 1) << 5;
            const int ns = st ^ 1;
            CP_ASYNC16(uA[ns],      Ap + koff);
            CP_ASYNC16(uA[ns] + 16, Ap + koff + 8);
            CP_ASYNC16(uB[ns],      Wp + (size_t)koff * N);
            CP_ASYNC16(uB[ns] + 16, Wp + (size_t)koff * N + 8);
            CP_COMMIT();
        }

        #pragma unroll
        for (int kk = 0; kk < 32; kk += 16) {
            wmma::fragment<wmma::matrix_b, 16, 16, 16, __half, wmma::row_major> bf[2];
            #pragma unroll
            for (int nj = 0; nj < 2; nj++)
                wmma::load_matrix_sync(bf[nj], &sm.p.Bs[st][kk][warp_n * 32 + nj * 16], HLDB);
            #pragma unroll
            for (int mi = 0; mi < 4; mi++) {
                wmma::fragment<wmma::matrix_a, 16, 16, 16, __half, wmma::row_major> af;
                wmma::load_matrix_sync(af, &sm.p.As[st][warp_m * 64 + mi * 16][kk], HLDA);
                #pragma unroll
                for (int nj = 0; nj < 2; nj++)
                    wmma::mma_sync(c[mi][nj], af, bf[nj], c[mi][nj]);
            }
        }
        st ^= 1;
    }
    __syncthreads();

    const int cg = col0 + warp_n * 32 + lane;
    const float bv = bias[cg];
    #pragma unroll
    for (int mi = 0; mi < 4; mi++) {
        wmma::store_matrix_sync(&sm.Cst[wid][0][0],  c[mi][0], LDC_S, wmma::mem_row_major);
        wmma::store_matrix_sync(&sm.Cst[wid][0][16], c[mi][1], LDC_S, wmma::mem_row_major);
        __syncwarp();
        const int rg0 = row0 + warp_m * 64 + mi * 16;
        #pragma unroll
        for (int rr = 0; rr < 16; rr++) {
            const int rg = rg0 + rr;
            float v = sm.Cst[wid][rr][lane] + bv;
            if (EPI == EPI_GELU) v = gelu_tanh(v);
            if (EPI == EPI_RES)  v += res[(size_t)rg * N + cg];
            if (sizeof(OutT) == 2)
                out[(size_t)rg * N + cg] = (OutT)__float2half(v);
            else
                out[(size_t)rg * N + cg] = (OutT)v;
        }
        __syncwarp();
    }
}

// ---------------------------------------------------------------------------
// Fused tensor-core attention: one block per (b,h, 64-query tile).
// S = Q@K^T (wmma) -> *0.125 + bias -> softmax -> P(fp16) -> P@V (wmma).
// Dynamic smem: Q(64x72h) K(256x72h) V(256x72h) S(64x264f); P aliases K,
// PV stage aliases S.
// ---------------------------------------------------------------------------
#define QLD 72     // halves
#define KLD 72
#define VLD 72
#define SLD 264    // floats
#define PLD 280    // halves
#define OFF_Q 0
#define OFF_K (OFF_Q + 64 * QLD * 2)                 // 9216
#define OFF_V (OFF_K + 256 * KLD * 2)                // 46080
#define OFF_S (OFF_V + 256 * VLD * 2)                // 82944
#define SMEM_ATTN (OFF_S + 64 * SLD * 4)             // 150528

__global__ __launch_bounds__(256) void attn_kernel(
    const __half* __restrict__ qkv, const float* __restrict__ bias_full,
    __half* __restrict__ attn_out)
{
    extern __shared__ char dyn[];
    __half* Qs = reinterpret_cast<__half*>(dyn + OFF_Q);
    __half* Ks = reinterpret_cast<__half*>(dyn + OFF_K);
    __half* Vs = reinterpret_cast<__half*>(dyn + OFF_V);
    float*  Ss = reinterpret_cast<float*>(dyn + OFF_S);
    __half* Ps = reinterpret_cast<__half*>(dyn + OFF_K);   // alias K
    float*  St = reinterpret_cast<float*>(dyn + OFF_S);    // PV stage, alias S

    const int bh = blockIdx.x;
    const int b  = bh >> 4, h = bh & 15;
    const int n0 = blockIdx.y * 64;
    const int tid = threadIdx.x;
    const int wid = tid >> 5;

    // ---- load Q (64x64), K (256x64), V (256x64) fp16
    #pragma unroll
    for (int i = tid; i < 64 * 8; i += 256) {
        const int r = i >> 3, c8 = (i & 7) * 8;
        *reinterpret_cast<float4*>(&Qs[r * QLD + c8]) =
            *reinterpret_cast<const float4*>(
                qkv + (size_t)(b * NTOK + n0 + r) * (3 * C_) + h * DH_ + c8);
    }
    #pragma unroll
    for (int i = tid; i < 256 * 8; i += 256) {
        const int r = i >> 3, c8 = (i & 7) * 8;
        *reinterpret_cast<float4*>(&Ks[r * KLD + c8]) =
            *reinterpret_cast<const float4*>(
                qkv + (size_t)(b * NTOK + r) * (3 * C_) + C_ + h * DH_ + c8);
        *reinterpret_cast<float4*>(&Vs[r * VLD + c8]) =
            *reinterpret_cast<const float4*>(
                qkv + (size_t)(b * NTOK + r) * (3 * C_) + 2 * C_ + h * DH_ + c8);
    }
    __syncthreads();

    // ---- S = Q @ K^T : warps 2x4, each 32 rows x 64 cols
    {
        const int warp_m = wid & 1;    // 0..1 -> 32-row slab
        const int warp_n = wid >> 1;   // 0..3 -> 64-col slab
        wmma::fragment<wmma::accumulator, 16, 16, 16, float> acc[2][4];
        #pragma unroll
        for (int mi = 0; mi < 2; mi++)
            #pragma unroll
            for (int nj = 0; nj < 4; nj++)
                wmma::fill_fragment(acc[mi][nj], 0.0f);
        #pragma unroll
        for (int kk = 0; kk < 64; kk += 16) {
            wmma::fragment<wmma::matrix_a, 16, 16, 16, __half, wmma::row_major> af[2];
            wmma::fragment<wmma::matrix_b, 16, 16, 16, __half, wmma::col_major> bf[4];
            #pragma unroll
            for (int mi = 0; mi < 2; mi++)
                wmma::load_matrix_sync(af[mi], &Qs[(warp_m * 32 + mi * 16) * QLD + kk], QLD);
            #pragma unroll
            for (int nj = 0; nj < 4; nj++)
                wmma::load_matrix_sync(bf[nj], &Ks[(warp_n * 64 + nj * 16) * KLD + kk], KLD);
            #pragma unroll
            for (int mi = 0; mi < 2; mi++)
                #pragma unroll
                for (int nj = 0; nj < 4; nj++)
                    wmma::mma_sync(acc[mi][nj], af[mi], bf[nj], acc[mi][nj]);
        }
        #pragma unroll
        for (int mi = 0; mi < 2; mi++)
            #pragma unroll
            for (int nj = 0; nj < 4; nj++)
                wmma::store_matrix_sync(
                    &Ss[(warp_m * 32 + mi * 16) * SLD + warp_n * 64 + nj * 16],
                    acc[mi][nj], SLD, wmma::mem_row_major);
    }
    __syncthreads();

    // ---- softmax rows; P = fp16, aliases K buffer
    {
        const int r  = tid >> 2;          // 0..63
        const int qq = tid & 3;           // quarter of the 256-wide row
        const float* bias_row = bias_full + (size_t)h * (NTOK * NTOK)
                              + (size_t)(n0 + r) * NTOK + qq * 64;
        float* srow = &Ss[r * SLD + qq * 64];

        float vmax = -1e30f;
        #pragma unroll
        for (int j = 0; j < 16; j++) {
            float4 s = *reinterpret_cast<float4*>(srow + j * 4);
            const float4 bb = *reinterpret_cast<const float4*>(bias_row + j * 4);
            s.x = s.x * 0.125f + bb.x; s.y = s.y * 0.125f + bb.y;
            s.z = s.z * 0.125f + bb.z; s.w = s.w * 0.125f + bb.w;
            *reinterpret_cast<float4*>(srow + j * 4) = s;
            vmax = fmaxf(vmax, fmaxf(fmaxf(s.x, s.y), fmaxf(s.z, s.w)));
        }
        vmax = fmaxf(vmax, __shfl_xor_sync(0xffffffffu, vmax, 1, 32));
        vmax = fmaxf(vmax, __shfl_xor_sync(0xffffffffu, vmax, 2, 32));

        float ssum = 0.0f;
        #pragma unroll
        for (int j = 0; j < 16; j++) {
            float4 s = *reinterpret_cast<float4*>(srow + j * 4);
            s.x = __expf(s.x - vmax); s.y = __expf(s.y - vmax);
            s.z = __expf(s.z - vmax); s.w = __expf(s.w - vmax);
            *reinterpret_cast<float4*>(srow + j * 4) = s;
            ssum += s.x + s.y + s.z + s.w;
        }
        ssum += __shfl_xor_sync(0xffffffffu, ssum, 1, 32);
        ssum += __shfl_xor_sync(0xffffffffu, ssum, 2, 32);
        const float inv = 1.0f / ssum;

        __half* prow = &Ps[r * PLD + qq * 64];
        #pragma unroll
        for (int j = 0; j < 16; j++) {
            const float4 s = *reinterpret_cast<float4*>(srow + j * 4);
            __half2 h0 = __floats2half2_rn(s.x * inv, s.y * inv);
            __half2 h1 = __floats2half2_rn(s.z * inv, s.w * inv);
            *reinterpret_cast<__half2*>(prow + j * 4)     = h0;
            *reinterpret_cast<__half2*>(prow + j * 4 + 2) = h1;
        }
    }
    __syncthreads();

    // ---- out = P @ V : warps 4x2, each 16 rows x 32 cols, k=256
    {
        const int warp_m = wid >> 1;   // 0..3 -> 16-row slab
        const int warp_n = wid & 1;    // 0..1 -> 32-col slab
        wmma::fragment<wmma::accumulator, 16, 16, 16, float> acc[2];
        wmma::fill_fragment(acc[0], 0.0f);
        wmma::fill_fragment(acc[1], 0.0f);
        #pragma unroll
        for (int k0 = 0; k0 < 256; k0 += 16) {
            wmma::fragment<wmma::matrix_a, 16, 16, 16, __half, wmma::row_major> af;
            wmma::load_matrix_sync(af, &Ps[(warp_m * 16) * PLD + k0], PLD);
            #pragma unroll
            for (int nj = 0; nj < 2; nj++) {
                wmma::fragment<wmma::matrix_b, 16, 16, 16, __half, wmma::row_major> bf;
                wmma::load_matrix_sync(bf, &Vs[k0 * VLD + warp_n * 32 + nj * 16], VLD);
                wmma::mma_sync(acc[nj], af, bf, acc[nj]);
            }
        }
        __syncthreads();   // S fully consumed by softmax; safe to overwrite stage
        #pragma unroll
        for (int nj = 0; nj < 2; nj++)
            wmma::store_matrix_sync(
                &St[(warp_m * 16) * QLD + warp_n * 32 + nj * 16],
                acc[nj], QLD, wmma::mem_row_major);
    }
    __syncthreads();

    // ---- write fp16 merged-head output
    {
        const int r  = tid >> 2;
        const int c0 = (tid & 3) * 16;
        __half tmp[16];
        #pragma unroll
        for (int j = 0; j < 16; j++)
            tmp[j] = __float2half(St[r * QLD + c0 + j]);
        __half* dst = attn_out + (size_t)(b * NTOK + n0 + r) * C_ + h * DH_ + c0;
        *reinterpret_cast<uint4*>(dst)     = *reinterpret_cast<uint4*>(&tmp[0]);
        *reinterpret_cast<uint4*>(dst + 8) = *reinterpret_cast<uint4*>(&tmp[8]);
    }
}

// ---------------------------------------------------------------------------
// Launch
// ---------------------------------------------------------------------------
extern "C" void kernel_launch(void* const* d_in, const int* in_sizes, int n_in,
                              void* d_out, int out_size)
{
    const float* x        = (const float*)d_in[0];
    const int*   rel_idx  = (const int*)  d_in[1];
    const float* qkv_w    = (const float*)d_in[2];
    const float* qkv_b    = (const float*)d_in[3];
    const float* proj_w   = (const float*)d_in[4];
    const float* proj_b   = (const float*)d_in[5];
    const float* rel_bias = (const float*)d_in[6];
    const float* ln1_g    = (const float*)d_in[7];
    const float* ln1_b    = (const float*)d_in[8];
    const float* ln2_g    = (const float*)d_in[9];
    const float* ln2_b    = (const float*)d_in[10];
    const float* fc1_w    = (const float*)d_in[11];
    const float* fc1_b    = (const float*)d_in[12];
    const float* fc2_w    = (const float*)d_in[13];
    const float* fc2_b    = (const float*)d_in[14];
    float* out = (float*)d_out;

    __half *lnh, *qkvh, *attnh, *ffh, *wh;
    float *x1, *biasf;
    cudaGetSymbolAddress((void**)&lnh,   g_lnh);
    cudaGetSymbolAddress((void**)&qkvh,  g_qkvh);
    cudaGetSymbolAddress((void**)&attnh, g_attnh);
    cudaGetSymbolAddress((void**)&x1,    g_x1);
    cudaGetSymbolAddress((void**)&ffh,   g_ffh);
    cudaGetSymbolAddress((void**)&wh,    g_wh);
    cudaGetSymbolAddress((void**)&biasf, g_bias);

    __half* qkv_wh  = wh;
    __half* proj_wh = wh + (size_t)3 * 1024 * 1024;
    __half* fc1_wh  = wh + (size_t)4 * 1024 * 1024;
    __half* fc2_wh  = wh + (size_t)8 * 1024 * 1024;

    static int attn_smem_set = 0;
    if (!attn_smem_set) {
        cudaFuncSetAttribute(attn_kernel,
            cudaFuncAttributeMaxDynamicSharedMemorySize, SMEM_ATTN);
        attn_smem_set = 1;
    }

    // 0) weight conversion + bias gather
    f2h_kernel<<<(3 * 1024 * 1024 / 4 + 255) / 256, 256>>>(qkv_w, qkv_wh, 3 * 1024 * 1024 / 4);
    f2h_kernel<<<(1024 * 1024 / 4 + 255) / 256, 256>>>(proj_w, proj_wh, 1024 * 1024 / 4);
    f2h_kernel<<<(4 * 1024 * 1024 / 4 + 255) / 256, 256>>>(fc1_w, fc1_wh, 4 * 1024 * 1024 / 4);
    f2h_kernel<<<(4 * 1024 * 1024 / 4 + 255) / 256, 256>>>(fc2_w, fc2_wh, 4 * 1024 * 1024 / 4);
    bias_gather_kernel<<<dim3(NTOK * NTOK / 256, H_), 256>>>(rel_idx, rel_bias, biasf);

    // 1) LN1 -> fp16
    ln_kernel<<<MTOK, 256>>>(x, ln1_g, ln1_b, lnh);
    // 2) QKV GEMM -> fp16 qkv
    hgemm<EPI_BIAS, __half><<<dim3(3 * C_ / 128, MTOK / 128), 256>>>(
        lnh, qkv_wh, qkv_b, nullptr, qkvh, MTOK, 3 * C_, C_);
    // 3) fused attention -> fp16 merged heads
    attn_kernel<<<dim3(B_ * H_, NTOK / 64), 256, SMEM_ATTN>>>(qkvh, biasf, attnh);
    // 4) proj + residual(x) -> x1 (fp32)
    hgemm<EPI_RES, float><<<dim3(C_ / 128, MTOK / 128), 256>>>(
        attnh, proj_wh, proj_b, x, x1, MTOK, C_, C_);
    // 5) LN2 -> fp16
    ln_kernel<<<MTOK, 256>>>(x1, ln2_g, ln2_b, lnh);
    // 6) FC1 + GELU -> fp16
    hgemm<EPI_GELU, __half><<<dim3(DFF_ / 128, MTOK / 128), 256>>>(
        lnh, fc1_wh, fc1_b, nullptr, ffh, MTOK, DFF_, C_);
    // 7) FC2 + residual(x1) -> out (fp32)
    hgemm<EPI_RES, float><<<dim3(C_ / 128, MTOK / 128), 256>>>(
        ffh, fc2_wh, fc2_b, x1, out, MTOK, C_, DFF_);
}

// round 16
// speedup vs baseline: 5.6203x; 1.0868x over previous
#include <cuda_runtime.h>
#include <cuda_fp16.h>
#include <math.h>
#include <stdint.h>
#include <mma.h>

using namespace nvcuda;

// Problem constants
#define B_     64
#define NTOK   256
#define C_     1024
#define H_     16
#define DH_    64
#define DFF_   4096
#define MTOK   (B_*NTOK)          // 16384 tokens
#define EPS_   1e-5f

// ---------------------------------------------------------------------------
// Scratch
// ---------------------------------------------------------------------------
__device__ __half g_lnh [(size_t)MTOK * C_];         //  32 MB LN out (fp16)
__device__ __half g_qkvh[(size_t)MTOK * 3 * C_];     //  96 MB qkv (fp16)
__device__ __half g_attnh[(size_t)MTOK * C_];        //  32 MB merged attn (fp16)
__device__ float  g_x1  [(size_t)MTOK * C_];         //  64 MB post-attn residual
__device__ __half g_ffh [(size_t)MTOK * DFF_];       // 128 MB MLP hidden (fp16)
__device__ __half g_wh  [(size_t)12 * 1024 * 1024];  //  24 MB fp16 weights
__device__ float  g_bias[(size_t)H_ * NTOK * NTOK];  //   4 MB gathered rel bias

// ---------------------------------------------------------------------------
// helpers
// ---------------------------------------------------------------------------
__device__ __forceinline__ uint32_t smem_u32(const void* p) {
    uint32_t a;
    asm("{ .reg .u64 t; cvta.to.shared.u64 t, %1; cvt.u32.u64 %0, t; }"
        : "=r"(a) : "l"(p));
    return a;
}
#define CP_ASYNC16(dst, src) \
    asm volatile("cp.async.cg.shared.global [%0], [%1], 16;" :: "r"(dst), "l"(src))
#define CP_COMMIT() asm volatile("cp.async.commit_group;" ::: "memory")
#define CP_WAIT1()  asm volatile("cp.async.wait_group 1;" ::: "memory")

__device__ __forceinline__ float tanh_fast(float x) {
    float y;
    asm("tanh.approx.f32 %0, %1;" : "=f"(y) : "f"(x));
    return y;
}

__global__ __launch_bounds__(256) void f2h_kernel(
    const float* __restrict__ src, __half* __restrict__ dst, int n4)
{
    const int i = blockIdx.x * 256 + threadIdx.x;
    if (i < n4) {
        const float4 v = reinterpret_cast<const float4*>(src)[i];
        reinterpret_cast<__half2*>(dst)[i * 2 + 0] = __floats2half2_rn(v.x, v.y);
        reinterpret_cast<__half2*>(dst)[i * 2 + 1] = __floats2half2_rn(v.z, v.w);
    }
}

// gathered bias: bf[h][n*256+m] = rel_bias[rel_idx[n*256+m]*H + h]
__global__ __launch_bounds__(256) void bias_gather_kernel(
    const int* __restrict__ rel_idx, const float* __restrict__ rel_bias,
    float* __restrict__ bf)
{
    const int i = blockIdx.x * 256 + threadIdx.x;   // 0..65535
    const int h = blockIdx.y;
    bf[(size_t)h * (NTOK * NTOK) + i] = rel_bias[rel_idx[i] * H_ + h];
}

// ---------------------------------------------------------------------------
// LayerNorm: warp per token (8 tokens/block), fp32 in, fp16 out
// ---------------------------------------------------------------------------
__global__ __launch_bounds__(256) void ln_kernel(
    const float* __restrict__ x, const float* __restrict__ g,
    const float* __restrict__ b, __half* __restrict__ out)
{
    const int tok  = blockIdx.x * 8 + (threadIdx.x >> 5);
    const int lane = threadIdx.x & 31;
    const float4* xr = reinterpret_cast<const float4*>(x + (size_t)tok * C_);

    float4 v[8];
    float s = 0.0f, ss = 0.0f;
    #pragma unroll
    for (int j = 0; j < 8; j++) {
        v[j] = xr[lane + j * 32];
        s  += v[j].x + v[j].y + v[j].z + v[j].w;
        ss += v[j].x*v[j].x + v[j].y*v[j].y + v[j].z*v[j].z + v[j].w*v[j].w;
    }
    #pragma unroll
    for (int o = 16; o > 0; o >>= 1) {
        s  += __shfl_xor_sync(0xffffffffu, s,  o, 32);
        ss += __shfl_xor_sync(0xffffffffu, ss, o, 32);
    }
    const float mu  = s * (1.0f / C_);
    const float var = ss * (1.0f / C_) - mu * mu;
    const float inv = rsqrtf(var + EPS_);

    const float4* gr = reinterpret_cast<const float4*>(g);
    const float4* br = reinterpret_cast<const float4*>(b);
    __half2* orow = reinterpret_cast<__half2*>(out + (size_t)tok * C_);
    #pragma unroll
    for (int j = 0; j < 8; j++) {
        const float4 gv = gr[lane + j * 32];
        const float4 bv = br[lane + j * 32];
        const int idx = (lane + j * 32) * 2;
        orow[idx + 0] = __floats2half2_rn((v[j].x - mu) * inv * gv.x + bv.x,
                                          (v[j].y - mu) * inv * gv.y + bv.y);
        orow[idx + 1] = __floats2half2_rn((v[j].z - mu) * inv * gv.z + bv.z,
                                          (v[j].w - mu) * inv * gv.w + bv.w);
    }
}

// ---------------------------------------------------------------------------
// FP16 WMMA GEMM, 3-stage cp.async pipeline (dynamic smem).
// out[M,N] = A[M,K](fp16) @ W[K,N](fp16) + bias (+gelu->fp16 | +res->fp32)
// 128x128 tile, BK=32, 256 threads = 8 warps (2x4), 64x32 per warp.
// ---------------------------------------------------------------------------
enum { EPI_BIAS = 0, EPI_GELU = 1, EPI_RES = 2 };

__device__ __forceinline__ float gelu_tanh(float x) {
    const float k0 = 0.7978845608028654f;
    float x3 = x * x * x;
    return 0.5f * x * (1.0f + tanh_fast(k0 * (x + 0.044715f * x3)));
}

#define HLDA 40
#define HLDB 136
#define LDC_S 40
#define AS_BYTES (3 * 128 * HLDA * 2)            // 30720
#define BS_BYTES (3 * 32 * HLDB * 2)             // 26112
#define SMEM_GEMM (AS_BYTES + BS_BYTES)          // 56832 (Cst 20480 aliases)

template <int EPI, typename OutT>
__global__ __launch_bounds__(256, 2) void hgemm(
    const __half* __restrict__ A, const __half* __restrict__ W,
    const float* __restrict__ bias, const float* __restrict__ res,
    OutT* __restrict__ out, int M, int N, int K)
{
    extern __shared__ char dynsm[];
    typedef __half AsT[128][HLDA];
    typedef __half BsT[32][HLDB];
    AsT* As = reinterpret_cast<AsT*>(dynsm);                // [3][128][HLDA]
    BsT* Bs = reinterpret_cast<BsT*>(dynsm + AS_BYTES);     // [3][32][HLDB]
    float (*Cst)[16][LDC_S] =
        reinterpret_cast<float(*)[16][LDC_S]>(dynsm);       // epilogue alias

    const int tid  = threadIdx.x;
    const int wid  = tid >> 5;
    const int lane = tid & 31;
    const int warp_m = wid & 1;
    const int warp_n = wid >> 1;
    const int row0 = blockIdx.y * 128;
    const int col0 = blockIdx.x * 128;

    const int arow = tid >> 1;
    const int acol = (tid & 1) * 16;
    const __half* Ap = A + (size_t)(row0 + arow) * K + acol;
    const int brow = tid >> 3;
    const int bcol = (tid & 7) * 16;
    const __half* Wp = W + (size_t)brow * N + col0 + bcol;

    uint32_t uA[3], uB[3];
    #pragma unroll
    for (int s = 0; s < 3; s++) {
        uA[s] = smem_u32(&As[s][arow][acol]);
        uB[s] = smem_u32(&Bs[s][brow][bcol]);
    }

    wmma::fragment<wmma::accumulator, 16, 16, 16, float> c[4][2];
    #pragma unroll
    for (int mi = 0; mi < 4; mi++)
        #pragma unroll
        for (int nj = 0; nj < 2; nj++)
            wmma::fill_fragment(c[mi][nj], 0.0f);

    const int n_iter = K >> 5;   // BK = 32

    // prologue: tiles 0,1 -> stages 0,1 (one commit group each)
    CP_ASYNC16(uA[0],      Ap);
    CP_ASYNC16(uA[0] + 16, Ap + 8);
    CP_ASYNC16(uB[0],      Wp);
    CP_ASYNC16(uB[0] + 16, Wp + 8);
    CP_COMMIT();
    CP_ASYNC16(uA[1],      Ap + 32);
    CP_ASYNC16(uA[1] + 16, Ap + 40);
    CP_ASYNC16(uB[1],      Wp + (size_t)32 * N);
    CP_ASYNC16(uB[1] + 16, Wp + (size_t)32 * N + 8);
    CP_COMMIT();

    int st = 0;
    for (int it = 0; it < n_iter; ++it) {
        CP_WAIT1();          // tile `it` resident (<=1 group pending)
        __syncthreads();     // everyone done with stage st from iter it-3

        if (it + 2 < n_iter) {
            const int ns = (st + 2 >= 3) ? st - 1 : st + 2;
            const size_t koff = (size_t)(it + 2) << 5;
            CP_ASYNC16(uA[ns],      Ap + koff);
            CP_ASYNC16(uA[ns] + 16, Ap + koff + 8);
            CP_ASYNC16(uB[ns],      Wp + koff * N);
            CP_ASYNC16(uB[ns] + 16, Wp + koff * N + 8);
        }
        CP_COMMIT();         // commit every iter to keep group count uniform

        #pragma unroll
        for (int kk = 0; kk < 32; kk += 16) {
            wmma::fragment<wmma::matrix_b, 16, 16, 16, __half, wmma::row_major> bf[2];
            #pragma unroll
            for (int nj = 0; nj < 2; nj++)
                wmma::load_matrix_sync(bf[nj], &Bs[st][kk][warp_n * 32 + nj * 16], HLDB);
            #pragma unroll
            for (int mi = 0; mi < 4; mi++) {
                wmma::fragment<wmma::matrix_a, 16, 16, 16, __half, wmma::row_major> af;
                wmma::load_matrix_sync(af, &As[st][warp_m * 64 + mi * 16][kk], HLDA);
                #pragma unroll
                for (int nj = 0; nj < 2; nj++)
                    wmma::mma_sync(c[mi][nj], af, bf[nj], c[mi][nj]);
            }
        }
        st = (st + 1 == 3) ? 0 : st + 1;
    }
    __syncthreads();   // compute done everywhere before Cst aliases stages

    const int cg = col0 + warp_n * 32 + lane;
    const float bv = bias[cg];
    #pragma unroll
    for (int mi = 0; mi < 4; mi++) {
        wmma::store_matrix_sync(&Cst[wid][0][0],  c[mi][0], LDC_S, wmma::mem_row_major);
        wmma::store_matrix_sync(&Cst[wid][0][16], c[mi][1], LDC_S, wmma::mem_row_major);
        __syncwarp();
        const int rg0 = row0 + warp_m * 64 + mi * 16;
        #pragma unroll
        for (int rr = 0; rr < 16; rr++) {
            const int rg = rg0 + rr;
            float v = Cst[wid][rr][lane] + bv;
            if (EPI == EPI_GELU) v = gelu_tanh(v);
            if (EPI == EPI_RES)  v += res[(size_t)rg * N + cg];
            if (sizeof(OutT) == 2)
                out[(size_t)rg * N + cg] = (OutT)__float2half(v);
            else
                out[(size_t)rg * N + cg] = (OutT)v;
        }
        __syncwarp();
    }
}

// ---------------------------------------------------------------------------
// Fused tensor-core attention (R10, known-good)
// ---------------------------------------------------------------------------
#define QLD 72
#define KLD 72
#define VLD 72
#define SLD 264
#define PLD 280
#define OFF_Q 0
#define OFF_K (OFF_Q + 64 * QLD * 2)
#define OFF_V (OFF_K + 256 * KLD * 2)
#define OFF_S (OFF_V + 256 * VLD * 2)
#define SMEM_ATTN (OFF_S + 64 * SLD * 4)

__global__ __launch_bounds__(256) void attn_kernel(
    const __half* __restrict__ qkv, const float* __restrict__ bias_full,
    __half* __restrict__ attn_out)
{
    extern __shared__ char dyn[];
    __half* Qs = reinterpret_cast<__half*>(dyn + OFF_Q);
    __half* Ks = reinterpret_cast<__half*>(dyn + OFF_K);
    __half* Vs = reinterpret_cast<__half*>(dyn + OFF_V);
    float*  Ss = reinterpret_cast<float*>(dyn + OFF_S);
    __half* Ps = reinterpret_cast<__half*>(dyn + OFF_K);   // alias K
    float*  St = reinterpret_cast<float*>(dyn + OFF_S);    // PV stage, alias S

    const int bh = blockIdx.x;
    const int b  = bh >> 4, h = bh & 15;
    const int n0 = blockIdx.y * 64;
    const int tid = threadIdx.x;
    const int wid = tid >> 5;

    #pragma unroll
    for (int i = tid; i < 64 * 8; i += 256) {
        const int r = i >> 3, c8 = (i & 7) * 8;
        *reinterpret_cast<float4*>(&Qs[r * QLD + c8]) =
            *reinterpret_cast<const float4*>(
                qkv + (size_t)(b * NTOK + n0 + r) * (3 * C_) + h * DH_ + c8);
    }
    #pragma unroll
    for (int i = tid; i < 256 * 8; i += 256) {
        const int r = i >> 3, c8 = (i & 7) * 8;
        *reinterpret_cast<float4*>(&Ks[r * KLD + c8]) =
            *reinterpret_cast<const float4*>(
                qkv + (size_t)(b * NTOK + r) * (3 * C_) + C_ + h * DH_ + c8);
        *reinterpret_cast<float4*>(&Vs[r * VLD + c8]) =
            *reinterpret_cast<const float4*>(
                qkv + (size_t)(b * NTOK + r) * (3 * C_) + 2 * C_ + h * DH_ + c8);
    }
    __syncthreads();

    {
        const int warp_m = wid & 1;
        const int warp_n = wid >> 1;
        wmma::fragment<wmma::accumulator, 16, 16, 16, float> acc[2][4];
        #pragma unroll
        for (int mi = 0; mi < 2; mi++)
            #pragma unroll
            for (int nj = 0; nj < 4; nj++)
                wmma::fill_fragment(acc[mi][nj], 0.0f);
        #pragma unroll
        for (int kk = 0; kk < 64; kk += 16) {
            wmma::fragment<wmma::matrix_a, 16, 16, 16, __half, wmma::row_major> af[2];
            wmma::fragment<wmma::matrix_b, 16, 16, 16, __half, wmma::col_major> bf[4];
            #pragma unroll
            for (int mi = 0; mi < 2; mi++)
                wmma::load_matrix_sync(af[mi], &Qs[(warp_m * 32 + mi * 16) * QLD + kk], QLD);
            #pragma unroll
            for (int nj = 0; nj < 4; nj++)
                wmma::load_matrix_sync(bf[nj], &Ks[(warp_n * 64 + nj * 16) * KLD + kk], KLD);
            #pragma unroll
            for (int mi = 0; mi < 2; mi++)
                #pragma unroll
                for (int nj = 0; nj < 4; nj++)
                    wmma::mma_sync(acc[mi][nj], af[mi], bf[nj], acc[mi][nj]);
        }
        #pragma unroll
        for (int mi = 0; mi < 2; mi++)
            #pragma unroll
            for (int nj = 0; nj < 4; nj++)
                wmma::store_matrix_sync(
                    &Ss[(warp_m * 32 + mi * 16) * SLD + warp_n * 64 + nj * 16],
                    acc[mi][nj], SLD, wmma::mem_row_major);
    }
    __syncthreads();

    {
        const int r  = tid >> 2;
        const int qq = tid & 3;
        const float* bias_row = bias_full + (size_t)h * (NTOK * NTOK)
                              + (size_t)(n0 + r) * NTOK + qq * 64;
        float* srow = &Ss[r * SLD + qq * 64];

        float vmax = -1e30f;
        #pragma unroll
        for (int j = 0; j < 16; j++) {
            float4 s = *reinterpret_cast<float4*>(srow + j * 4);
            const float4 bb = *reinterpret_cast<const float4*>(bias_row + j * 4);
            s.x = s.x * 0.125f + bb.x; s.y = s.y * 0.125f + bb.y;
            s.z = s.z * 0.125f + bb.z; s.w = s.w * 0.125f + bb.w;
            *reinterpret_cast<float4*>(srow + j * 4) = s;
            vmax = fmaxf(vmax, fmaxf(fmaxf(s.x, s.y), fmaxf(s.z, s.w)));
        }
        vmax = fmaxf(vmax, __shfl_xor_sync(0xffffffffu, vmax, 1, 32));
        vmax = fmaxf(vmax, __shfl_xor_sync(0xffffffffu, vmax, 2, 32));

        float ssum = 0.0f;
        #pragma unroll
        for (int j = 0; j < 16; j++) {
            float4 s = *reinterpret_cast<float4*>(srow + j * 4);
            s.x = __expf(s.x - vmax); s.y = __expf(s.y - vmax);
            s.z = __expf(s.z - vmax); s.w = __expf(s.w - vmax);
            *reinterpret_cast<float4*>(srow + j * 4) = s;
            ssum += s.x + s.y + s.z + s.w;
        }
        ssum += __shfl_xor_sync(0xffffffffu, ssum, 1, 32);
        ssum += __shfl_xor_sync(0xffffffffu, ssum, 2, 32);
        const float inv = 1.0f / ssum;

        __half* prow = &Ps[r * PLD + qq * 64];
        #pragma unroll
        for (int j = 0; j < 16; j++) {
            const float4 s = *reinterpret_cast<float4*>(srow + j * 4);
            *reinterpret_cast<__half2*>(prow + j * 4)     = __floats2half2_rn(s.x * inv, s.y * inv);
            *reinterpret_cast<__half2*>(prow + j * 4 + 2) = __floats2half2_rn(s.z * inv, s.w * inv);
        }
    }
    __syncthreads();

    {
        const int warp_m = wid >> 1;
        const int warp_n = wid & 1;
        wmma::fragment<wmma::accumulator, 16, 16, 16, float> acc[2];
        wmma::fill_fragment(acc[0], 0.0f);
        wmma::fill_fragment(acc[1], 0.0f);
        #pragma unroll
        for (int k0 = 0; k0 < 256; k0 += 16) {
            wmma::fragment<wmma::matrix_a, 16, 16, 16, __half, wmma::row_major> af;
            wmma::load_matrix_sync(af, &Ps[(warp_m * 16) * PLD + k0], PLD);
            #pragma unroll
            for (int nj = 0; nj < 2; nj++) {
                wmma::fragment<wmma::matrix_b, 16, 16, 16, __half, wmma::row_major> bf;
                wmma::load_matrix_sync(bf, &Vs[k0 * VLD + warp_n * 32 + nj * 16], VLD);
                wmma::mma_sync(acc[nj], af, bf, acc[nj]);
            }
        }
        __syncthreads();
        #pragma unroll
        for (int nj = 0; nj < 2; nj++)
            wmma::store_matrix_sync(
                &St[(warp_m * 16) * QLD + warp_n * 32 + nj * 16],
                acc[nj], QLD, wmma::mem_row_major);
    }
    __syncthreads();

    {
        const int r  = tid >> 2;
        const int c0 = (tid & 3) * 16;
        __half tmp[16];
        #pragma unroll
        for (int j = 0; j < 16; j++)
            tmp[j] = __float2half(St[r * QLD + c0 + j]);
        __half* dst = attn_out + (size_t)(b * NTOK + n0 + r) * C_ + h * DH_ + c0;
        *reinterpret_cast<uint4*>(dst)     = *reinterpret_cast<uint4*>(&tmp[0]);
        *reinterpret_cast<uint4*>(dst + 8) = *reinterpret_cast<uint4*>(&tmp[8]);
    }
}

// ---------------------------------------------------------------------------
// Launch
// ---------------------------------------------------------------------------
extern "C" void kernel_launch(void* const* d_in, const int* in_sizes, int n_in,
                              void* d_out, int out_size)
{
    const float* x        = (const float*)d_in[0];
    const int*   rel_idx  = (const int*)  d_in[1];
    const float* qkv_w    = (const float*)d_in[2];
    const float* qkv_b    = (const float*)d_in[3];
    const float* proj_w   = (const float*)d_in[4];
    const float* proj_b   = (const float*)d_in[5];
    const float* rel_bias = (const float*)d_in[6];
    const float* ln1_g    = (const float*)d_in[7];
    const float* ln1_b    = (const float*)d_in[8];
    const float* ln2_g    = (const float*)d_in[9];
    const float* ln2_b    = (const float*)d_in[10];
    const float* fc1_w    = (const float*)d_in[11];
    const float* fc1_b    = (const float*)d_in[12];
    const float* fc2_w    = (const float*)d_in[13];
    const float* fc2_b    = (const float*)d_in[14];
    float* out = (float*)d_out;

    __half *lnh, *qkvh, *attnh, *ffh, *wh;
    float *x1, *biasf;
    cudaGetSymbolAddress((void**)&lnh,   g_lnh);
    cudaGetSymbolAddress((void**)&qkvh,  g_qkvh);
    cudaGetSymbolAddress((void**)&attnh, g_attnh);
    cudaGetSymbolAddress((void**)&x1,    g_x1);
    cudaGetSymbolAddress((void**)&ffh,   g_ffh);
    cudaGetSymbolAddress((void**)&wh,    g_wh);
    cudaGetSymbolAddress((void**)&biasf, g_bias);

    __half* qkv_wh  = wh;
    __half* proj_wh = wh + (size_t)3 * 1024 * 1024;
    __half* fc1_wh  = wh + (size_t)4 * 1024 * 1024;
    __half* fc2_wh  = wh + (size_t)8 * 1024 * 1024;

    cudaFuncSetAttribute(attn_kernel,
        cudaFuncAttributeMaxDynamicSharedMemorySize, SMEM_ATTN);
    cudaFuncSetAttribute(hgemm<EPI_BIAS, __half>,
        cudaFuncAttributeMaxDynamicSharedMemorySize, SMEM_GEMM);
    cudaFuncSetAttribute(hgemm<EPI_RES, float>,
        cudaFuncAttributeMaxDynamicSharedMemorySize, SMEM_GEMM);
    cudaFuncSetAttribute(hgemm<EPI_GELU, __half>,
        cudaFuncAttributeMaxDynamicSharedMemorySize, SMEM_GEMM);

    // 0) weight conversion + bias gather
    f2h_kernel<<<(3 * 1024 * 1024 / 4 + 255) / 256, 256>>>(qkv_w, qkv_wh, 3 * 1024 * 1024 / 4);
    f2h_kernel<<<(1024 * 1024 / 4 + 255) / 256, 256>>>(proj_w, proj_wh, 1024 * 1024 / 4);
    f2h_kernel<<<(4 * 1024 * 1024 / 4 + 255) / 256, 256>>>(fc1_w, fc1_wh, 4 * 1024 * 1024 / 4);
    f2h_kernel<<<(4 * 1024 * 1024 / 4 + 255) / 256, 256>>>(fc2_w, fc2_wh, 4 * 1024 * 1024 / 4);
    bias_gather_kernel<<<dim3(NTOK * NTOK / 256, H_), 256>>>(rel_idx, rel_bias, biasf);

    // 1) LN1 -> fp16
    ln_kernel<<<MTOK / 8, 256>>>(x, ln1_g, ln1_b, lnh);
    // 2) QKV GEMM -> fp16 qkv
    hgemm<EPI_BIAS, __half><<<dim3(3 * C_ / 128, MTOK / 128), 256, SMEM_GEMM>>>(
        lnh, qkv_wh, qkv_b, nullptr, qkvh, MTOK, 3 * C_, C_);
    // 3) fused attention -> fp16 merged heads
    attn_kernel<<<dim3(B_ * H_, NTOK / 64), 256, SMEM_ATTN>>>(qkvh, biasf, attnh);
    // 4) proj + residual(x) -> x1 (fp32)
    hgemm<EPI_RES, float><<<dim3(C_ / 128, MTOK / 128), 256, SMEM_GEMM>>>(
        attnh, proj_wh, proj_b, x, x1, MTOK, C_, C_);
    // 5) LN2 -> fp16
    ln_kernel<<<MTOK / 8, 256>>>(x1, ln2_g, ln2_b, lnh);
    // 6) FC1 + GELU -> fp16
    hgemm<EPI_GELU, __half><<<dim3(DFF_ / 128, MTOK / 128), 256, SMEM_GEMM>>>(
        lnh, fc1_wh, fc1_b, nullptr, ffh, MTOK, DFF_, C_);
    // 7) FC2 + residual(x1) -> out (fp32)
    hgemm<EPI_RES, float><<<dim3(C_ / 128, MTOK / 128), 256, SMEM_GEMM>>>(
        ffh, fc2_wh, fc2_b, x1, out, MTOK, C_, DFF_);
}